// round 13
// baseline (speedup 1.0000x reference)
#include <cuda_runtime.h>
#include <cstddef>

// ---------------- problem constants ----------------
#define DD0 41
#define DD1 20          // (41-3)/2+1
#define DD2 9           // (20-3)/2+1
#define HH  200
#define WW  176
#define HWs 35200
#define EPSV 1e-3f

#define N0MAX 30016
#define N1MAX 60032     // <= 2*N0
#define N2MAX 120064    // <= 2*M1
#define TCAP  65536     // per-tap pair capacity (>= max pairs per tap, proven)

#define MAP0_SZ (2*DD0*HWs)   // 2,886,400
#define MAP1_SZ (2*DD1*HWs)   // 1,408,000
#define MAP2_SZ (2*DD2*HWs)   //   633,600
#define OUT_TOTAL (2*64*DD2*HWs)

// ---------------- device scratch ----------------
__device__ __align__(16) int   g_map0[MAP0_SZ];
__device__ __align__(16) int   g_map1[MAP1_SZ];
__device__ __align__(16) int   g_map2[MAP2_SZ];

__device__ __align__(16) float g_Y0[(size_t)N0MAX*64];
__device__ __align__(16) float g_Z1[(size_t)N1MAX*64];
__device__ __align__(16) float g_YA[(size_t)N1MAX*64];
__device__ __align__(16) float g_YB[(size_t)N1MAX*64];
__device__ __align__(16) float g_Z2[(size_t)N2MAX*64];

__device__ __align__(16) int4  g_c1[N1MAX];
__device__ __align__(16) int4  g_c2[N2MAX];

__device__ __align__(16) int2  g_p0[27*TCAP];
__device__ __align__(16) int2  g_p1[27*TCAP];
__device__ __align__(16) int2  g_zp1[3*TCAP];
__device__ __align__(16) int2  g_zp2[3*TCAP];
__device__ int   g_pc0[27];
__device__ int   g_pc1[27];
__device__ int   g_zc1[3];
__device__ int   g_zc2[3];
__device__ int   g_cnt[4];          // [0]=N0  [1]=M1  [2]=M2
__device__ float g_stats[5*128];    // per BN layer: 64 sums + 64 sumsqs

// ---------------- init (maps + counters only) ----------------
__global__ void k_init(int n0) {
    size_t tid = (size_t)blockIdx.x*blockDim.x + threadIdx.x;
    size_t stride = (size_t)gridDim.x*blockDim.x;
    int4 z4 = make_int4(0,0,0,0);
    int4* m0 = (int4*)g_map0;
    for (size_t i = tid; i < MAP0_SZ/4; i += stride) m0[i] = z4;
    int4* m1 = (int4*)g_map1;
    for (size_t i = tid; i < MAP1_SZ/4; i += stride) m1[i] = z4;
    int4* m2 = (int4*)g_map2;
    for (size_t i = tid; i < MAP2_SZ/4; i += stride) m2[i] = z4;
    if (tid < 27) { g_pc0[tid] = 0; g_pc1[tid] = 0; }
    if (tid < 3)  { g_zc1[tid] = 0; g_zc2[tid] = 0; }
    if (tid < 5*128) g_stats[tid] = 0.0f;
    if (tid == 0) { g_cnt[0] = n0; g_cnt[1] = 0; g_cnt[2] = 0; g_cnt[3] = 0; }
}

// ---------------- map build (+ zero Y0 rows) ----------------
__global__ void k_map0(const int4* __restrict__ coors, int n0) {
    int i = blockIdx.x*256 + threadIdx.x;
    if (i >= n0) return;
    int4 c = coors[i];
    g_map0[((c.x*DD0 + c.y)*HH + c.z)*WW + c.w] = i + 1;
    float4 z = make_float4(0.f,0.f,0.f,0.f);
    float4* yp = (float4*)(g_Y0 + (size_t)i*64);
    #pragma unroll
    for (int q = 0; q < 16; q++) yp[q] = z;
}

__global__ void k_build0(const int4* __restrict__ coors, int n0) {
    int i = blockIdx.x*256 + threadIdx.x;
    if (i >= n0) return;
    int4 c = coors[i];
    int b = c.x, z = c.y, y = c.z, x = c.w;
    #pragma unroll
    for (int dz = -1; dz <= 1; dz++)
    #pragma unroll
    for (int dy = -1; dy <= 1; dy++)
    #pragma unroll
    for (int dx = -1; dx <= 1; dx++) {
        int t = (dz+1)*9 + (dy+1)*3 + (dx+1);
        if (t == 13) continue;
        int nz = z+dz, ny = y+dy, nx = x+dx;
        if (nz < 0 || nz >= DD0 || ny < 0 || ny >= HH || nx < 0 || nx >= WW) continue;
        int j = g_map0[((b*DD0 + nz)*HH + ny)*WW + nx] - 1;
        if (j >= 0) {
            int pos = atomicAdd(&g_pc0[t], 1);
            g_p0[t*TCAP + pos] = make_int2(j, i);
        }
    }
    #pragma unroll
    for (int kz = 0; kz < 3; kz++) {
        int tt = z - kz;
        if (tt >= 0 && (tt & 1) == 0) {
            int oz = tt >> 1;
            if (oz < DD1) g_map1[((b*DD1 + oz)*HH + y)*WW + x] = 1;
        }
    }
}

// z-conv pair build: input row -> output row per kz
__global__ void k_zbuild1(const int4* __restrict__ coors, int n0) {
    int i = blockIdx.x*256 + threadIdx.x;
    if (i >= n0) return;
    int4 c = coors[i];
    #pragma unroll
    for (int kz = 0; kz < 3; kz++) {
        int tt = c.y - kz;
        if (tt >= 0 && (tt & 1) == 0) {
            int oz = tt >> 1;
            if (oz < DD1) {
                int dst = g_map1[((c.x*DD1 + oz)*HH + c.z)*WW + c.w] - 2;
                if (dst >= 0) {
                    int pos = atomicAdd(&g_zc1[kz], 1);
                    g_zp1[kz*TCAP + pos] = make_int2(i, dst);
                }
            }
        }
    }
}

__global__ void k_zbuild2() {
    int r = blockIdx.x*256 + threadIdx.x;
    if (r >= g_cnt[1]) return;
    int4 c = g_c1[r];
    #pragma unroll
    for (int kz = 0; kz < 3; kz++) {
        int tt = c.y - kz;
        if (tt >= 0 && (tt & 1) == 0) {
            int oz = tt >> 1;
            if (oz < DD2) {
                int dst = g_map2[((c.x*DD2 + oz)*HH + c.z)*WW + c.w] - 2;
                if (dst >= 0) {
                    int pos = atomicAdd(&g_zc2[kz], 1);
                    g_zp2[kz*TCAP + pos] = make_int2(r, dst);
                }
            }
        }
    }
}

// subm stage-1 pair build + mark map2 + zero YA/YB rows
__global__ void k_build1() {
    int r = blockIdx.x*256 + threadIdx.x;
    if (r >= g_cnt[1]) return;
    int4 c = g_c1[r];
    int b = c.x, z = c.y, y = c.z, x = c.w;
    #pragma unroll
    for (int dz = -1; dz <= 1; dz++)
    #pragma unroll
    for (int dy = -1; dy <= 1; dy++)
    #pragma unroll
    for (int dx = -1; dx <= 1; dx++) {
        int t = (dz+1)*9 + (dy+1)*3 + (dx+1);
        if (t == 13) continue;
        int nz = z+dz, ny = y+dy, nx = x+dx;
        if (nz < 0 || nz >= DD1 || ny < 0 || ny >= HH || nx < 0 || nx >= WW) continue;
        int j = g_map1[((b*DD1 + nz)*HH + ny)*WW + nx] - 2;
        if (j >= 0) {
            int pos = atomicAdd(&g_pc1[t], 1);
            g_p1[t*TCAP + pos] = make_int2(j, r);
        }
    }
    #pragma unroll
    for (int kz = 0; kz < 3; kz++) {
        int tt = z - kz;
        if (tt >= 0 && (tt & 1) == 0) {
            int oz = tt >> 1;
            if (oz < DD2) g_map2[((b*DD2 + oz)*HH + y)*WW + x] = 1;
        }
    }
    float4 zf = make_float4(0.f,0.f,0.f,0.f);
    float4* ya = (float4*)(g_YA + (size_t)r*64);
    float4* yb = (float4*)(g_YB + (size_t)r*64);
    #pragma unroll
    for (int q = 0; q < 16; q++) { ya[q] = zf; yb[q] = zf; }
}

// ---------------- compact marked map -> row ids + coords (+ zero Z rows) ----------------
__global__ void k_compact(int which) {
    int* map   = which ? g_map2 : g_map1;
    int size4  = which ? MAP2_SZ/4 : MAP1_SZ/4;
    int D      = which ? DD2 : DD1;
    int4* cout = which ? g_c2 : g_c1;
    float* zbuf = which ? g_Z2 : g_Z1;
    int ci     = which ? 2 : 1;
    __shared__ int scnt, sbase;
    int gid = blockIdx.x*256 + threadIdx.x;
    if (threadIdx.x == 0) scnt = 0;
    __syncthreads();
    bool in = gid < size4;
    int4 v = make_int4(0,0,0,0);
    if (in) v = ((int4*)map)[gid];
    int vals[4] = {v.x, v.y, v.z, v.w};
    int my = (vals[0]==1) + (vals[1]==1) + (vals[2]==1) + (vals[3]==1);
    int loc = 0;
    if (my) loc = atomicAdd(&scnt, my);
    __syncthreads();
    if (threadIdx.x == 0) sbase = scnt ? atomicAdd(&g_cnt[ci], scnt) : 0;
    __syncthreads();
    if (!in) return;
    if (my) {
        int idx = sbase + loc;
        int lin = gid*4;
        int outv[4];
        float4 zf = make_float4(0.f,0.f,0.f,0.f);
        #pragma unroll
        for (int q = 0; q < 4; q++) {
            if (vals[q] == 1) {
                int L = lin + q;
                int b = L / (D*HWs);
                int r = L % (D*HWs);
                int z = r / HWs;
                int rr = r % HWs;
                int y = rr / WW;
                int x = rr % WW;
                cout[idx] = make_int4(b, z, y, x);
                float4* zp = (float4*)(zbuf + (size_t)idx*64);
                #pragma unroll
                for (int qq = 0; qq < 16; qq++) zp[qq] = zf;
                outv[q] = idx + 2;
                idx++;
            } else outv[q] = 0;
        }
        ((int4*)map)[gid] = make_int4(outv[0], outv[1], outv[2], outv[3]);
    }
}

// ---------------- merged tiled conv kernel ----------------
// grid.y = taps; centerTap uses identity rows; all writes atomicAdd into
// zero-initialized Y.
// Template TB = threads/block; tile = TB/4 rows x 64 channels.
// Staging: thread t owns row p = t % ROWS, float4 range [g*NQ4,(g+1)*NQ4),
// g = t / ROWS (4 groups). Compute: cq=t&15 (4 channels), rg=t>>4 (4 rows).
// If layer >= 0: BN(layer, count g_cnt[bnci])+ReLU applied to X while staging.
template<int K, int TB>
__global__ __launch_bounds__(TB, 2) void k_conv(const float* __restrict__ X,
        const float* __restrict__ Wsrc, float* __restrict__ Y,
        const int2* __restrict__ pairsB, const int* __restrict__ pcnt, int ci,
        int centerTap, int layer, int bnci,
        const float* __restrict__ gm, const float* __restrict__ bt) {
    extern __shared__ float sm[];
    constexpr int ROWS = TB/4;
    constexpr int RP   = ROWS + 4;
    constexpr int NQ4  = K/16;
    float* sW = sm;               // K*64 floats
    float* sF = sm + K*64;        // K*RP floats, layout [k][row]
    __shared__ float ssc[64], sbi[64];

    const bool isC = ((int)blockIdx.y == centerTap);
    const int total = isC ? g_cnt[ci] : pcnt[blockIdx.y];
    if ((int)blockIdx.x * ROWS >= total) return;   // idle block: no weight load
    const int2* pairs = pairsB + (size_t)blockIdx.y*TCAP;
    const float* Wp = Wsrc + (size_t)blockIdx.y*(K*64);

    if (layer >= 0 && threadIdx.x < 64) {
        int c = threadIdx.x;
        float cn = fmaxf((float)g_cnt[bnci], 1.0f);
        float mean = g_stats[layer*128 + c] / cn;
        float var  = g_stats[layer*128 + 64 + c] / cn - mean*mean;
        float sc   = gm[c] * rsqrtf(var + EPSV);
        ssc[c] = sc;
        sbi[c] = bt[c] - mean*sc;
    }
    for (int i = threadIdx.x; i < K*16; i += TB)
        ((float4*)sW)[i] = ((const float4*)Wp)[i];

    const float4* Xv = (const float4*)X;
    const int p  = threadIdx.x % ROWS;
    const int g  = threadIdx.x / ROWS;
    const int cq = threadIdx.x & 15;
    const int rg = threadIdx.x >> 4;
    const int gstride = gridDim.x * ROWS;

    float4 st[NQ4];
    auto prefetch = [&](int pb) {
        if (pb >= total) return;
        int pnr = total - pb; if (pnr > ROWS) pnr = ROWS;
        if (p >= pnr) {
            #pragma unroll
            for (int qi = 0; qi < NQ4; qi++) st[qi] = make_float4(0.f,0.f,0.f,0.f);
            return;
        }
        int row = isC ? (pb + p) : pairs[pb + p].x;
        const float4* xp = Xv + (size_t)row*(K/4) + g*NQ4;
        #pragma unroll
        for (int qi = 0; qi < NQ4; qi++) st[qi] = xp[qi];
    };

    prefetch(blockIdx.x*ROWS);

    for (int base = blockIdx.x*ROWS; base < total; base += gstride) {
        int nr = min(ROWS, total - base);
        __syncthreads();     // sW/BN coeffs ready (iter0) / prev compute done
        #pragma unroll
        for (int qi = 0; qi < NQ4; qi++) {
            int q4 = g*NQ4 + qi;
            float4 v = st[qi];
            if (layer >= 0) {
                int c4 = (q4*4) & 63;
                v.x = fmaxf(fmaf(v.x, ssc[c4+0], sbi[c4+0]), 0.f);
                v.y = fmaxf(fmaf(v.y, ssc[c4+1], sbi[c4+1]), 0.f);
                v.z = fmaxf(fmaf(v.z, ssc[c4+2], sbi[c4+2]), 0.f);
                v.w = fmaxf(fmaf(v.w, ssc[c4+3], sbi[c4+3]), 0.f);
            }
            float* d = sF + (q4*4)*RP + p;
            d[0] = v.x; d[RP] = v.y;
            d[2*RP] = v.z; d[3*RP] = v.w;
        }
        __syncthreads();
        prefetch(base + gstride);

        float4 a0 = make_float4(0.f,0.f,0.f,0.f);
        float4 a1 = a0, a2 = a0, a3 = a0;
        const float4* wv = (const float4*)sW;
        float4 wA = wv[cq];
        float4 fA = *(const float4*)(sF + rg*4);
        #pragma unroll 8
        for (int k = 0; k < K; k++) {
            float4 wB, fB;
            if (k < K-1) {
                wB = wv[(k+1)*16 + cq];
                fB = *(const float4*)(sF + (k+1)*RP + rg*4);
            }
            a0.x += fA.x*wA.x; a0.y += fA.x*wA.y; a0.z += fA.x*wA.z; a0.w += fA.x*wA.w;
            a1.x += fA.y*wA.x; a1.y += fA.y*wA.y; a1.z += fA.y*wA.z; a1.w += fA.y*wA.w;
            a2.x += fA.z*wA.x; a2.y += fA.z*wA.y; a2.z += fA.z*wA.z; a2.w += fA.z*wA.w;
            a3.x += fA.w*wA.x; a3.y += fA.w*wA.y; a3.z += fA.w*wA.z; a3.w += fA.w*wA.w;
            wA = wB; fA = fB;
        }
        int p0 = rg*4;
        #pragma unroll
        for (int r = 0; r < 4; r++) {
            if (p0 + r < nr) {
                float4 a = (r==0)?a0:(r==1)?a1:(r==2)?a2:a3;
                int dst = isC ? (base + p0 + r) : pairs[base + p0 + r].y;
                float* yp = Y + (size_t)dst*64 + cq*4;
                atomicAdd(yp+0, a.x); atomicAdd(yp+1, a.y);
                atomicAdd(yp+2, a.z); atomicAdd(yp+3, a.w);
            }
        }
    }
}

// ---------------- BN stats ----------------
__global__ void k_stats(const float* __restrict__ X, int ci, int layer) {
    __shared__ float ss[512];
    int cnt = g_cnt[ci];
    int c = threadIdx.x & 63, g = threadIdx.x >> 6;
    float s = 0.f, q = 0.f;
    for (int r = blockIdx.x*4 + g; r < cnt; r += gridDim.x*4) {
        float v = X[(size_t)r*64 + c];
        s += v; q += v*v;
    }
    ss[threadIdx.x] = s; ss[256 + threadIdx.x] = q;
    __syncthreads();
    if (threadIdx.x < 64) {
        s = ss[threadIdx.x] + ss[threadIdx.x+64] + ss[threadIdx.x+128] + ss[threadIdx.x+192];
        q = ss[256+threadIdx.x] + ss[320+threadIdx.x] + ss[384+threadIdx.x] + ss[448+threadIdx.x];
        atomicAdd(&g_stats[layer*128 + threadIdx.x], s);
        atomicAdd(&g_stats[layer*128 + 64 + threadIdx.x], q);
    }
}

// ---------------- final: BN + ReLU + dense scatter (fused) ----------------
__global__ void k_out(const float* __restrict__ Z2, float* __restrict__ out,
                      const float* __restrict__ gm, const float* __restrict__ bt) {
    __shared__ float ssc[64], sbi[64];
    int cnt = g_cnt[2];
    float cn = fmaxf((float)cnt, 1.0f);
    if (threadIdx.x < 64) {
        int c = threadIdx.x;
        float mean = g_stats[512 + c] / cn;
        float var  = g_stats[512 + 64 + c] / cn - mean*mean;
        float sc   = gm[c] * rsqrtf(var + EPSV);
        ssc[c] = sc;
        sbi[c] = bt[c] - mean*sc;
    }
    __syncthreads();
    const int tot4 = OUT_TOTAL/4;
    for (int e4 = blockIdx.x*blockDim.x + threadIdx.x; e4 < tot4;
         e4 += gridDim.x*blockDim.x) {
        int e = e4 * 4;
        int x  = e % WW;
        int t1 = e / WW;
        int y  = t1 % HH;
        int t2 = t1 / HH;
        int cz = t2 % (64*DD2);
        int b  = t2 / (64*DD2);
        int c  = cz / DD2;
        int z  = cz - c*DD2;
        float sc = ssc[c], bi = sbi[c];
        int midx = ((b*DD2 + z)*HH + y)*WW + x;
        int4 m = *reinterpret_cast<const int4*>(g_map2 + midx);
        float4 o;
        int j;
        j = m.x - 2; o.x = (j >= 0) ? fmaxf(fmaf(Z2[(size_t)j*64 + c], sc, bi), 0.f) : 0.f;
        j = m.y - 2; o.y = (j >= 0) ? fmaxf(fmaf(Z2[(size_t)j*64 + c], sc, bi), 0.f) : 0.f;
        j = m.z - 2; o.z = (j >= 0) ? fmaxf(fmaf(Z2[(size_t)j*64 + c], sc, bi), 0.f) : 0.f;
        j = m.w - 2; o.w = (j >= 0) ? fmaxf(fmaf(Z2[(size_t)j*64 + c], sc, bi), 0.f) : 0.f;
        ((float4*)out)[e4] = o;
    }
}

// ---------------- launch ----------------
extern "C" void kernel_launch(void* const* d_in, const int* in_sizes, int n_in,
                              void* d_out, int out_size) {
    const float* vox   = (const float*)d_in[0];
    const int4*  coors = (const int4*) d_in[1];
    const float* w0    = (const float*)d_in[3];
    const float* gg0   = (const float*)d_in[4];
    const float* bb0   = (const float*)d_in[5];
    const float* ws1   = (const float*)d_in[6];
    const float* ggs1  = (const float*)d_in[7];
    const float* bbs1  = (const float*)d_in[8];
    const float* w1a   = (const float*)d_in[9];
    const float* gg1a  = (const float*)d_in[10];
    const float* bb1a  = (const float*)d_in[11];
    const float* w1b   = (const float*)d_in[12];
    const float* gg1b  = (const float*)d_in[13];
    const float* bb1b  = (const float*)d_in[14];
    const float* ws2   = (const float*)d_in[15];
    const float* ggs2  = (const float*)d_in[16];
    const float* bbs2  = (const float*)d_in[17];
    float* out = (float*)d_out;
    int n0 = in_sizes[0] / 128;

    void *pY0, *pZ1, *pYA, *pYB, *pZ2, *pp0, *pp1, *pzp1, *pzp2,
         *ppc0, *ppc1, *pzc1, *pzc2;
    cudaGetSymbolAddress(&pY0, g_Y0);
    cudaGetSymbolAddress(&pZ1, g_Z1);
    cudaGetSymbolAddress(&pYA, g_YA);
    cudaGetSymbolAddress(&pYB, g_YB);
    cudaGetSymbolAddress(&pZ2, g_Z2);
    cudaGetSymbolAddress(&pp0, g_p0);
    cudaGetSymbolAddress(&pp1, g_p1);
    cudaGetSymbolAddress(&pzp1, g_zp1);
    cudaGetSymbolAddress(&pzp2, g_zp2);
    cudaGetSymbolAddress(&ppc0, g_pc0);
    cudaGetSymbolAddress(&ppc1, g_pc1);
    cudaGetSymbolAddress(&pzc1, g_zc1);
    cudaGetSymbolAddress(&pzc2, g_zc2);
    float* Y0 = (float*)pY0; float* Z1 = (float*)pZ1;
    float* YA = (float*)pYA; float* YB = (float*)pYB; float* Z2 = (float*)pZ2;
    const int2* P0 = (const int2*)pp0;  const int2* P1 = (const int2*)pp1;
    const int2* ZP1 = (const int2*)pzp1; const int2* ZP2 = (const int2*)pzp2;
    const int* PC0 = (const int*)ppc0;  const int* PC1 = (const int*)ppc1;
    const int* ZC1 = (const int*)pzc1;  const int* ZC2 = (const int*)pzc2;

    // second stream + events (created once; no device memory allocation)
    static cudaStream_t sB = nullptr;
    static cudaEvent_t evFork = nullptr, evZ1 = nullptr, evB1 = nullptr, evZ2 = nullptr;
    if (sB == nullptr) {
        cudaStreamCreateWithFlags(&sB, cudaStreamNonBlocking);
        cudaEventCreateWithFlags(&evFork, cudaEventDisableTiming);
        cudaEventCreateWithFlags(&evZ1,   cudaEventDisableTiming);
        cudaEventCreateWithFlags(&evB1,   cudaEventDisableTiming);
        cudaEventCreateWithFlags(&evZ2,   cudaEventDisableTiming);
    }
    cudaStream_t s0 = 0;   // legacy default stream (harness captures this)

    // smem: conv0 (K=128, TB=256, RP=68): 128*(64+68)*4 = 67584
    //       K=64, TB=512, RP=132: 64*(64+132)*4 = 50176
    const int SM0 = 128*(64+68)*4;
    const int SM1 = 64*(64+132)*4;
    cudaFuncSetAttribute((const void*)k_conv<128,256>, cudaFuncAttributeMaxDynamicSharedMemorySize, SM0);
    cudaFuncSetAttribute((const void*)k_conv<64,512>,  cudaFuncAttributeMaxDynamicSharedMemorySize, SM1);

    int gb0 = (n0 + 255) / 256;
    int gt0 = (n0 + 63) / 64;            // conv0 center tiles (64-row)
    int gt1 = (N1MAX + 127) / 128;       // 469: stage-1 center tiles (128-row)

    // ---- serial prologue on s0 ----
    k_init<<<1024, 256, 0, s0>>>(n0);
    k_map0<<<gb0, 256, 0, s0>>>(coors, n0);
    k_build0<<<gb0, 256, 0, s0>>>(coors, n0);

    // ---- fork: track B (maps/pair builds) runs concurrently with convs ----
    cudaEventRecord(evFork, s0);
    cudaStreamWaitEvent(sB, evFork, 0);

    // track B: compact1 -> zbuild1 -> [evZ1] -> build1 -> [evB1] -> compact2 -> zbuild2 -> [evZ2]
    k_compact<<<MAP1_SZ/4/256, 256, 0, sB>>>(0);
    k_zbuild1<<<gb0, 256, 0, sB>>>(coors, n0);
    cudaEventRecord(evZ1, sB);
    k_build1<<<(N1MAX+255)/256, 256, 0, sB>>>();
    cudaEventRecord(evB1, sB);
    k_compact<<<(MAP2_SZ/4 + 255)/256, 256, 0, sB>>>(1);
    k_zbuild2<<<(N1MAX+255)/256, 256, 0, sB>>>();
    cudaEventRecord(evZ2, sB);

    // track A (s0): stage 0 subm 128->64, merged 27 taps, K=128 (64-row tiles)
    k_conv<128,256><<<dim3(gt0,27), 256, SM0, s0>>>(vox, w0, Y0,
            P0, PC0, 0, 13, -1, 0, nullptr, nullptr);
    k_stats<<<256, 256, 0, s0>>>(Y0, 0, 0);

    // stride-z conv 1 (needs zbuild1/compact1 from track B), 128-row tiles
    cudaStreamWaitEvent(s0, evZ1, 0);
    k_conv<64,512><<<dim3(120,3), 512, SM1, s0>>>(Y0, ws1, Z1,
            ZP1, ZC1, 1, -1, 0, 0, gg0, bb0);
    k_stats<<<256, 256, 0, s0>>>(Z1, 1, 1);

    // subm1a (needs build1 pairs + YA zeroed), 128-row tiles
    cudaStreamWaitEvent(s0, evB1, 0);
    k_conv<64,512><<<dim3(gt1,27), 512, SM1, s0>>>(Z1, w1a, YA,
            P1, PC1, 1, 13, 1, 1, ggs1, bbs1);
    k_stats<<<256, 256, 0, s0>>>(YA, 1, 2);

    // subm1b, 128-row tiles
    k_conv<64,512><<<dim3(gt1,27), 512, SM1, s0>>>(YA, w1b, YB,
            P1, PC1, 1, 13, 2, 1, gg1a, bb1a);
    k_stats<<<256, 256, 0, s0>>>(YB, 1, 3);

    // stride-z conv 2 (needs compact2/zbuild2 from track B), 128-row tiles
    cudaStreamWaitEvent(s0, evZ2, 0);
    k_conv<64,512><<<dim3(176,3), 512, SM1, s0>>>(YB, ws2, Z2,
            ZP2, ZC2, 2, -1, 3, 1, gg1b, bb1b);
    k_stats<<<256, 256, 0, s0>>>(Z2, 2, 4);

    // fused BN4 + ReLU + dense scatter
    k_out<<<2368, 256, 0, s0>>>(Z2, out, ggs2, bbs2);

    (void)n_in; (void)out_size;
}

// round 14
// speedup vs baseline: 1.0691x; 1.0691x over previous
#include <cuda_runtime.h>
#include <cstddef>

// ---------------- problem constants ----------------
#define DD0 41
#define DD1 20          // (41-3)/2+1
#define DD2 9           // (20-3)/2+1
#define HH  200
#define WW  176
#define HWs 35200
#define EPSV 1e-3f

#define N0MAX 30016
#define N1MAX 60032     // <= 2*N0
#define N2MAX 120064    // <= 2*M1
#define TCAP  65536     // per-tap pair capacity (>= max pairs per tap, proven)

#define MAP0_SZ (2*DD0*HWs)   // 2,886,400
#define MAP1_SZ (2*DD1*HWs)   // 1,408,000
#define MAP2_SZ (2*DD2*HWs)   //   633,600
#define OUT_TOTAL (2*64*DD2*HWs)

// ---------------- device scratch ----------------
__device__ __align__(16) int   g_map0[MAP0_SZ];
__device__ __align__(16) int   g_map1[MAP1_SZ];
__device__ __align__(16) int   g_map2[MAP2_SZ];

__device__ __align__(16) float g_Y0[(size_t)N0MAX*64];
__device__ __align__(16) float g_Z1[(size_t)N1MAX*64];
__device__ __align__(16) float g_YA[(size_t)N1MAX*64];
__device__ __align__(16) float g_YB[(size_t)N1MAX*64];
__device__ __align__(16) float g_Z2[(size_t)N2MAX*64];

__device__ __align__(16) int4  g_c1[N1MAX];
__device__ __align__(16) int4  g_c2[N2MAX];

__device__ __align__(16) int2  g_p0[27*TCAP];
__device__ __align__(16) int2  g_p1[27*TCAP];
__device__ __align__(16) int2  g_zp1[3*TCAP];
__device__ __align__(16) int2  g_zp2[3*TCAP];
__device__ int   g_pc0[27];
__device__ int   g_pc1[27];
__device__ int   g_zc1[3];
__device__ int   g_zc2[3];
__device__ int   g_cnt[4];          // [0]=N0  [1]=M1  [2]=M2
__device__ float g_stats[5*128];    // per BN layer: 64 sums + 64 sumsqs

// ---------------- init (maps + counters only) ----------------
__global__ void k_init(int n0) {
    size_t tid = (size_t)blockIdx.x*blockDim.x + threadIdx.x;
    size_t stride = (size_t)gridDim.x*blockDim.x;
    int4 z4 = make_int4(0,0,0,0);
    int4* m0 = (int4*)g_map0;
    for (size_t i = tid; i < MAP0_SZ/4; i += stride) m0[i] = z4;
    int4* m1 = (int4*)g_map1;
    for (size_t i = tid; i < MAP1_SZ/4; i += stride) m1[i] = z4;
    int4* m2 = (int4*)g_map2;
    for (size_t i = tid; i < MAP2_SZ/4; i += stride) m2[i] = z4;
    if (tid < 27) { g_pc0[tid] = 0; g_pc1[tid] = 0; }
    if (tid < 3)  { g_zc1[tid] = 0; g_zc2[tid] = 0; }
    if (tid < 5*128) g_stats[tid] = 0.0f;
    if (tid == 0) { g_cnt[0] = n0; g_cnt[1] = 0; g_cnt[2] = 0; g_cnt[3] = 0; }
}

// ---------------- map build (+ zero Y0 rows) ----------------
__global__ void k_map0(const int4* __restrict__ coors, int n0) {
    int i = blockIdx.x*256 + threadIdx.x;
    if (i >= n0) return;
    int4 c = coors[i];
    g_map0[((c.x*DD0 + c.y)*HH + c.z)*WW + c.w] = i + 1;
    float4 z = make_float4(0.f,0.f,0.f,0.f);
    float4* yp = (float4*)(g_Y0 + (size_t)i*64);
    #pragma unroll
    for (int q = 0; q < 16; q++) yp[q] = z;
}

__global__ void k_build0(const int4* __restrict__ coors, int n0) {
    int i = blockIdx.x*256 + threadIdx.x;
    if (i >= n0) return;
    int4 c = coors[i];
    int b = c.x, z = c.y, y = c.z, x = c.w;
    #pragma unroll
    for (int dz = -1; dz <= 1; dz++)
    #pragma unroll
    for (int dy = -1; dy <= 1; dy++)
    #pragma unroll
    for (int dx = -1; dx <= 1; dx++) {
        int t = (dz+1)*9 + (dy+1)*3 + (dx+1);
        if (t == 13) continue;
        int nz = z+dz, ny = y+dy, nx = x+dx;
        if (nz < 0 || nz >= DD0 || ny < 0 || ny >= HH || nx < 0 || nx >= WW) continue;
        int j = g_map0[((b*DD0 + nz)*HH + ny)*WW + nx] - 1;
        if (j >= 0) {
            int pos = atomicAdd(&g_pc0[t], 1);
            g_p0[t*TCAP + pos] = make_int2(j, i);
        }
    }
    #pragma unroll
    for (int kz = 0; kz < 3; kz++) {
        int tt = z - kz;
        if (tt >= 0 && (tt & 1) == 0) {
            int oz = tt >> 1;
            if (oz < DD1) g_map1[((b*DD1 + oz)*HH + y)*WW + x] = 1;
        }
    }
}

// z-conv pair build: input row -> output row per kz
__global__ void k_zbuild1(const int4* __restrict__ coors, int n0) {
    int i = blockIdx.x*256 + threadIdx.x;
    if (i >= n0) return;
    int4 c = coors[i];
    #pragma unroll
    for (int kz = 0; kz < 3; kz++) {
        int tt = c.y - kz;
        if (tt >= 0 && (tt & 1) == 0) {
            int oz = tt >> 1;
            if (oz < DD1) {
                int dst = g_map1[((c.x*DD1 + oz)*HH + c.z)*WW + c.w] - 2;
                if (dst >= 0) {
                    int pos = atomicAdd(&g_zc1[kz], 1);
                    g_zp1[kz*TCAP + pos] = make_int2(i, dst);
                }
            }
        }
    }
}

__global__ void k_zbuild2() {
    int r = blockIdx.x*256 + threadIdx.x;
    if (r >= g_cnt[1]) return;
    int4 c = g_c1[r];
    #pragma unroll
    for (int kz = 0; kz < 3; kz++) {
        int tt = c.y - kz;
        if (tt >= 0 && (tt & 1) == 0) {
            int oz = tt >> 1;
            if (oz < DD2) {
                int dst = g_map2[((c.x*DD2 + oz)*HH + c.z)*WW + c.w] - 2;
                if (dst >= 0) {
                    int pos = atomicAdd(&g_zc2[kz], 1);
                    g_zp2[kz*TCAP + pos] = make_int2(r, dst);
                }
            }
        }
    }
}

// subm stage-1 pair build + mark map2 + zero YA/YB rows
__global__ void k_build1() {
    int r = blockIdx.x*256 + threadIdx.x;
    if (r >= g_cnt[1]) return;
    int4 c = g_c1[r];
    int b = c.x, z = c.y, y = c.z, x = c.w;
    #pragma unroll
    for (int dz = -1; dz <= 1; dz++)
    #pragma unroll
    for (int dy = -1; dy <= 1; dy++)
    #pragma unroll
    for (int dx = -1; dx <= 1; dx++) {
        int t = (dz+1)*9 + (dy+1)*3 + (dx+1);
        if (t == 13) continue;
        int nz = z+dz, ny = y+dy, nx = x+dx;
        if (nz < 0 || nz >= DD1 || ny < 0 || ny >= HH || nx < 0 || nx >= WW) continue;
        int j = g_map1[((b*DD1 + nz)*HH + ny)*WW + nx] - 2;
        if (j >= 0) {
            int pos = atomicAdd(&g_pc1[t], 1);
            g_p1[t*TCAP + pos] = make_int2(j, r);
        }
    }
    #pragma unroll
    for (int kz = 0; kz < 3; kz++) {
        int tt = z - kz;
        if (tt >= 0 && (tt & 1) == 0) {
            int oz = tt >> 1;
            if (oz < DD2) g_map2[((b*DD2 + oz)*HH + y)*WW + x] = 1;
        }
    }
    float4 zf = make_float4(0.f,0.f,0.f,0.f);
    float4* ya = (float4*)(g_YA + (size_t)r*64);
    float4* yb = (float4*)(g_YB + (size_t)r*64);
    #pragma unroll
    for (int q = 0; q < 16; q++) { ya[q] = zf; yb[q] = zf; }
}

// ---------------- compact marked map -> row ids + coords (+ zero Z rows) ----------------
__global__ void k_compact(int which) {
    int* map   = which ? g_map2 : g_map1;
    int size4  = which ? MAP2_SZ/4 : MAP1_SZ/4;
    int D      = which ? DD2 : DD1;
    int4* cout = which ? g_c2 : g_c1;
    float* zbuf = which ? g_Z2 : g_Z1;
    int ci     = which ? 2 : 1;
    __shared__ int scnt, sbase;
    int gid = blockIdx.x*256 + threadIdx.x;
    if (threadIdx.x == 0) scnt = 0;
    __syncthreads();
    bool in = gid < size4;
    int4 v = make_int4(0,0,0,0);
    if (in) v = ((int4*)map)[gid];
    int vals[4] = {v.x, v.y, v.z, v.w};
    int my = (vals[0]==1) + (vals[1]==1) + (vals[2]==1) + (vals[3]==1);
    int loc = 0;
    if (my) loc = atomicAdd(&scnt, my);
    __syncthreads();
    if (threadIdx.x == 0) sbase = scnt ? atomicAdd(&g_cnt[ci], scnt) : 0;
    __syncthreads();
    if (!in) return;
    if (my) {
        int idx = sbase + loc;
        int lin = gid*4;
        int outv[4];
        float4 zf = make_float4(0.f,0.f,0.f,0.f);
        #pragma unroll
        for (int q = 0; q < 4; q++) {
            if (vals[q] == 1) {
                int L = lin + q;
                int b = L / (D*HWs);
                int r = L % (D*HWs);
                int z = r / HWs;
                int rr = r % HWs;
                int y = rr / WW;
                int x = rr % WW;
                cout[idx] = make_int4(b, z, y, x);
                float4* zp = (float4*)(zbuf + (size_t)idx*64);
                #pragma unroll
                for (int qq = 0; qq < 16; qq++) zp[qq] = zf;
                outv[q] = idx + 2;
                idx++;
            } else outv[q] = 0;
        }
        ((int4*)map)[gid] = make_int4(outv[0], outv[1], outv[2], outv[3]);
    }
}

// ---------------- merged tiled conv kernel ----------------
// grid.y = taps; centerTap uses identity rows; all writes atomicAdd into
// zero-initialized Y. Tile: 64 rows x 64 channels per block of 256 threads.
// Center blocks may process multiple tiles via grid-stride (amortizes the
// per-block weight prologue); tap blocks early-exit before the weight load.
// Staging: thread t owns row p=t&63, float4 range [g*NQ4,(g+1)*NQ4), g=t>>6.
// Compute: cq=t&15 (4 channels), rg=t>>4 (4 rows), pipelined scalar FFMA.
// If layer >= 0: BN(layer, count g_cnt[bnci])+ReLU applied to X while staging.
#define RP2 68
template<int K>
__global__ __launch_bounds__(256) void k_conv(const float* __restrict__ X,
        const float* __restrict__ Wsrc, float* __restrict__ Y,
        const int2* __restrict__ pairsB, const int* __restrict__ pcnt, int ci,
        int centerTap, int layer, int bnci,
        const float* __restrict__ gm, const float* __restrict__ bt) {
    extern __shared__ float sm[];
    float* sW = sm;               // K*64 floats
    float* sF = sm + K*64;        // K*RP2 floats, layout [k][row]
    __shared__ float ssc[64], sbi[64];

    constexpr int NQ4 = K/16;

    const bool isC = ((int)blockIdx.y == centerTap);
    const int total = isC ? g_cnt[ci] : pcnt[blockIdx.y];
    if ((int)blockIdx.x * 64 >= total) return;   // idle block: no weight load
    const int2* pairs = pairsB + (size_t)blockIdx.y*TCAP;
    const float* Wp = Wsrc + (size_t)blockIdx.y*(K*64);

    if (layer >= 0 && threadIdx.x < 64) {
        int c = threadIdx.x;
        float cn = fmaxf((float)g_cnt[bnci], 1.0f);
        float mean = g_stats[layer*128 + c] / cn;
        float var  = g_stats[layer*128 + 64 + c] / cn - mean*mean;
        float sc   = gm[c] * rsqrtf(var + EPSV);
        ssc[c] = sc;
        sbi[c] = bt[c] - mean*sc;
    }
    for (int i = threadIdx.x; i < K*16; i += 256)
        ((float4*)sW)[i] = ((const float4*)Wp)[i];

    const float4* Xv = (const float4*)X;
    const int p  = threadIdx.x & 63;
    const int g  = threadIdx.x >> 6;
    const int cq = threadIdx.x & 15;
    const int rg = threadIdx.x >> 4;
    const int gstride = gridDim.x * 64;

    float4 st[NQ4];
    auto prefetch = [&](int pb) {
        if (pb >= total) return;
        int pnr = total - pb; if (pnr > 64) pnr = 64;
        if (p >= pnr) {
            #pragma unroll
            for (int qi = 0; qi < NQ4; qi++) st[qi] = make_float4(0.f,0.f,0.f,0.f);
            return;
        }
        int row = isC ? (pb + p) : pairs[pb + p].x;
        const float4* xp = Xv + (size_t)row*(K/4) + g*NQ4;
        #pragma unroll
        for (int qi = 0; qi < NQ4; qi++) st[qi] = xp[qi];
    };

    prefetch(blockIdx.x*64);

    for (int base = blockIdx.x*64; base < total; base += gstride) {
        int nr = min(64, total - base);
        __syncthreads();     // sW/BN coeffs ready (iter0) / prev compute done
        #pragma unroll
        for (int qi = 0; qi < NQ4; qi++) {
            int q4 = g*NQ4 + qi;
            float4 v = st[qi];
            if (layer >= 0) {
                int c4 = (q4*4) & 63;
                v.x = fmaxf(fmaf(v.x, ssc[c4+0], sbi[c4+0]), 0.f);
                v.y = fmaxf(fmaf(v.y, ssc[c4+1], sbi[c4+1]), 0.f);
                v.z = fmaxf(fmaf(v.z, ssc[c4+2], sbi[c4+2]), 0.f);
                v.w = fmaxf(fmaf(v.w, ssc[c4+3], sbi[c4+3]), 0.f);
            }
            float* d = sF + (q4*4)*RP2 + p;
            d[0] = v.x; d[RP2] = v.y;
            d[2*RP2] = v.z; d[3*RP2] = v.w;
        }
        __syncthreads();
        prefetch(base + gstride);

        float4 a0 = make_float4(0.f,0.f,0.f,0.f);
        float4 a1 = a0, a2 = a0, a3 = a0;
        const float4* wv = (const float4*)sW;
        float4 wA = wv[cq];
        float4 fA = *(const float4*)(sF + rg*4);
        #pragma unroll 8
        for (int k = 0; k < K; k++) {
            float4 wB, fB;
            if (k < K-1) {
                wB = wv[(k+1)*16 + cq];
                fB = *(const float4*)(sF + (k+1)*RP2 + rg*4);
            }
            a0.x += fA.x*wA.x; a0.y += fA.x*wA.y; a0.z += fA.x*wA.z; a0.w += fA.x*wA.w;
            a1.x += fA.y*wA.x; a1.y += fA.y*wA.y; a1.z += fA.y*wA.z; a1.w += fA.y*wA.w;
            a2.x += fA.z*wA.x; a2.y += fA.z*wA.y; a2.z += fA.z*wA.z; a2.w += fA.z*wA.w;
            a3.x += fA.w*wA.x; a3.y += fA.w*wA.y; a3.z += fA.w*wA.z; a3.w += fA.w*wA.w;
            wA = wB; fA = fB;
        }
        int p0 = rg*4;
        #pragma unroll
        for (int r = 0; r < 4; r++) {
            if (p0 + r < nr) {
                float4 a = (r==0)?a0:(r==1)?a1:(r==2)?a2:a3;
                int dst = isC ? (base + p0 + r) : pairs[base + p0 + r].y;
                float* yp = Y + (size_t)dst*64 + cq*4;
                atomicAdd(yp+0, a.x); atomicAdd(yp+1, a.y);
                atomicAdd(yp+2, a.z); atomicAdd(yp+3, a.w);
            }
        }
    }
}

// ---------------- BN stats ----------------
__global__ void k_stats(const float* __restrict__ X, int ci, int layer) {
    __shared__ float ss[512];
    int cnt = g_cnt[ci];
    int c = threadIdx.x & 63, g = threadIdx.x >> 6;
    float s = 0.f, q = 0.f;
    for (int r = blockIdx.x*4 + g; r < cnt; r += gridDim.x*4) {
        float v = X[(size_t)r*64 + c];
        s += v; q += v*v;
    }
    ss[threadIdx.x] = s; ss[256 + threadIdx.x] = q;
    __syncthreads();
    if (threadIdx.x < 64) {
        s = ss[threadIdx.x] + ss[threadIdx.x+64] + ss[threadIdx.x+128] + ss[threadIdx.x+192];
        q = ss[256+threadIdx.x] + ss[320+threadIdx.x] + ss[384+threadIdx.x] + ss[448+threadIdx.x];
        atomicAdd(&g_stats[layer*128 + threadIdx.x], s);
        atomicAdd(&g_stats[layer*128 + 64 + threadIdx.x], q);
    }
}

// ---------------- final: BN + ReLU + dense scatter (fused) ----------------
__global__ void k_out(const float* __restrict__ Z2, float* __restrict__ out,
                      const float* __restrict__ gm, const float* __restrict__ bt) {
    __shared__ float ssc[64], sbi[64];
    int cnt = g_cnt[2];
    float cn = fmaxf((float)cnt, 1.0f);
    if (threadIdx.x < 64) {
        int c = threadIdx.x;
        float mean = g_stats[512 + c] / cn;
        float var  = g_stats[512 + 64 + c] / cn - mean*mean;
        float sc   = gm[c] * rsqrtf(var + EPSV);
        ssc[c] = sc;
        sbi[c] = bt[c] - mean*sc;
    }
    __syncthreads();
    const int tot4 = OUT_TOTAL/4;
    for (int e4 = blockIdx.x*blockDim.x + threadIdx.x; e4 < tot4;
         e4 += gridDim.x*blockDim.x) {
        int e = e4 * 4;
        int x  = e % WW;
        int t1 = e / WW;
        int y  = t1 % HH;
        int t2 = t1 / HH;
        int cz = t2 % (64*DD2);
        int b  = t2 / (64*DD2);
        int c  = cz / DD2;
        int z  = cz - c*DD2;
        float sc = ssc[c], bi = sbi[c];
        int midx = ((b*DD2 + z)*HH + y)*WW + x;
        int4 m = *reinterpret_cast<const int4*>(g_map2 + midx);
        float4 o;
        int j;
        j = m.x - 2; o.x = (j >= 0) ? fmaxf(fmaf(Z2[(size_t)j*64 + c], sc, bi), 0.f) : 0.f;
        j = m.y - 2; o.y = (j >= 0) ? fmaxf(fmaf(Z2[(size_t)j*64 + c], sc, bi), 0.f) : 0.f;
        j = m.z - 2; o.z = (j >= 0) ? fmaxf(fmaf(Z2[(size_t)j*64 + c], sc, bi), 0.f) : 0.f;
        j = m.w - 2; o.w = (j >= 0) ? fmaxf(fmaf(Z2[(size_t)j*64 + c], sc, bi), 0.f) : 0.f;
        ((float4*)out)[e4] = o;
    }
}

// ---------------- launch ----------------
extern "C" void kernel_launch(void* const* d_in, const int* in_sizes, int n_in,
                              void* d_out, int out_size) {
    const float* vox   = (const float*)d_in[0];
    const int4*  coors = (const int4*) d_in[1];
    const float* w0    = (const float*)d_in[3];
    const float* gg0   = (const float*)d_in[4];
    const float* bb0   = (const float*)d_in[5];
    const float* ws1   = (const float*)d_in[6];
    const float* ggs1  = (const float*)d_in[7];
    const float* bbs1  = (const float*)d_in[8];
    const float* w1a   = (const float*)d_in[9];
    const float* gg1a  = (const float*)d_in[10];
    const float* bb1a  = (const float*)d_in[11];
    const float* w1b   = (const float*)d_in[12];
    const float* gg1b  = (const float*)d_in[13];
    const float* bb1b  = (const float*)d_in[14];
    const float* ws2   = (const float*)d_in[15];
    const float* ggs2  = (const float*)d_in[16];
    const float* bbs2  = (const float*)d_in[17];
    float* out = (float*)d_out;
    int n0 = in_sizes[0] / 128;

    void *pY0, *pZ1, *pYA, *pYB, *pZ2, *pp0, *pp1, *pzp1, *pzp2,
         *ppc0, *ppc1, *pzc1, *pzc2;
    cudaGetSymbolAddress(&pY0, g_Y0);
    cudaGetSymbolAddress(&pZ1, g_Z1);
    cudaGetSymbolAddress(&pYA, g_YA);
    cudaGetSymbolAddress(&pYB, g_YB);
    cudaGetSymbolAddress(&pZ2, g_Z2);
    cudaGetSymbolAddress(&pp0, g_p0);
    cudaGetSymbolAddress(&pp1, g_p1);
    cudaGetSymbolAddress(&pzp1, g_zp1);
    cudaGetSymbolAddress(&pzp2, g_zp2);
    cudaGetSymbolAddress(&ppc0, g_pc0);
    cudaGetSymbolAddress(&ppc1, g_pc1);
    cudaGetSymbolAddress(&pzc1, g_zc1);
    cudaGetSymbolAddress(&pzc2, g_zc2);
    float* Y0 = (float*)pY0; float* Z1 = (float*)pZ1;
    float* YA = (float*)pYA; float* YB = (float*)pYB; float* Z2 = (float*)pZ2;
    const int2* P0 = (const int2*)pp0;  const int2* P1 = (const int2*)pp1;
    const int2* ZP1 = (const int2*)pzp1; const int2* ZP2 = (const int2*)pzp2;
    const int* PC0 = (const int*)ppc0;  const int* PC1 = (const int*)ppc1;
    const int* ZC1 = (const int*)pzc1;  const int* ZC2 = (const int*)pzc2;

    // second stream + events (created once; no device memory allocation)
    static cudaStream_t sB = nullptr;
    static cudaEvent_t evFork = nullptr, evZ1 = nullptr, evB1 = nullptr, evZ2 = nullptr;
    if (sB == nullptr) {
        cudaStreamCreateWithFlags(&sB, cudaStreamNonBlocking);
        cudaEventCreateWithFlags(&evFork, cudaEventDisableTiming);
        cudaEventCreateWithFlags(&evZ1,   cudaEventDisableTiming);
        cudaEventCreateWithFlags(&evB1,   cudaEventDisableTiming);
        cudaEventCreateWithFlags(&evZ2,   cudaEventDisableTiming);
    }
    cudaStream_t s0 = 0;   // legacy default stream (harness captures this)

    // dynamic smem = K*(64+RP2)*4 = K*528 bytes
    cudaFuncSetAttribute(k_conv<128>, cudaFuncAttributeMaxDynamicSharedMemorySize, 128*528);
    cudaFuncSetAttribute(k_conv<64>,  cudaFuncAttributeMaxDynamicSharedMemorySize, 64*528);

    int gb0 = (n0 + 255) / 256;
    int gtc = (n0 + 127) / 128;         // conv0 center: 2 tiles/block (235)
    int gts = (N1MAX + 127) / 128;      // stage-1 subm: 2 tiles/block (469)

    // ---- serial prologue on s0 ----
    k_init<<<1024, 256, 0, s0>>>(n0);
    k_map0<<<gb0, 256, 0, s0>>>(coors, n0);
    k_build0<<<gb0, 256, 0, s0>>>(coors, n0);

    // ---- fork: track B (maps/pair builds) runs concurrently with convs ----
    cudaEventRecord(evFork, s0);
    cudaStreamWaitEvent(sB, evFork, 0);

    // track B: compact1 -> zbuild1 -> [evZ1] -> build1 -> [evB1] -> compact2 -> zbuild2 -> [evZ2]
    k_compact<<<MAP1_SZ/4/256, 256, 0, sB>>>(0);
    k_zbuild1<<<gb0, 256, 0, sB>>>(coors, n0);
    cudaEventRecord(evZ1, sB);
    k_build1<<<(N1MAX+255)/256, 256, 0, sB>>>();
    cudaEventRecord(evB1, sB);
    k_compact<<<(MAP2_SZ/4 + 255)/256, 256, 0, sB>>>(1);
    k_zbuild2<<<(N1MAX+255)/256, 256, 0, sB>>>();
    cudaEventRecord(evZ2, sB);

    // track A (s0): stage 0 subm 128->64, merged 27 taps, K=128, 2 tiles/block
    k_conv<128><<<dim3(gtc,27), 256, 128*528, s0>>>(vox, w0, Y0,
            P0, PC0, 0, 13, -1, 0, nullptr, nullptr);
    k_stats<<<256, 256, 0, s0>>>(Y0, 0, 0);

    // stride-z conv 1 (needs zbuild1/compact1 from track B)
    cudaStreamWaitEvent(s0, evZ1, 0);
    k_conv<64><<<dim3(96,3), 256, 64*528, s0>>>(Y0, ws1, Z1,
            ZP1, ZC1, 1, -1, 0, 0, gg0, bb0);
    k_stats<<<256, 256, 0, s0>>>(Z1, 1, 1);

    // subm1a (needs build1 pairs + YA zeroed), 2 tiles/block on center
    cudaStreamWaitEvent(s0, evB1, 0);
    k_conv<64><<<dim3(gts,27), 256, 64*528, s0>>>(Z1, w1a, YA,
            P1, PC1, 1, 13, 1, 1, ggs1, bbs1);
    k_stats<<<256, 256, 0, s0>>>(YA, 1, 2);

    // subm1b, 2 tiles/block on center
    k_conv<64><<<dim3(gts,27), 256, 64*528, s0>>>(YA, w1b, YB,
            P1, PC1, 1, 13, 2, 1, gg1a, bb1a);
    k_stats<<<256, 256, 0, s0>>>(YB, 1, 3);

    // stride-z conv 2 (needs compact2/zbuild2 from track B)
    cudaStreamWaitEvent(s0, evZ2, 0);
    k_conv<64><<<dim3(192,3), 256, 64*528, s0>>>(YB, ws2, Z2,
            ZP2, ZC2, 2, -1, 3, 1, gg1b, bb1b);
    k_stats<<<256, 256, 0, s0>>>(Z2, 2, 4);

    // fused BN4 + ReLU + dense scatter
    k_out<<<2368, 256, 0, s0>>>(Z2, out, ggs2, bbs2);

    (void)n_in; (void)out_size;
}

// round 15
// speedup vs baseline: 1.0871x; 1.0168x over previous
#include <cuda_runtime.h>
#include <cstddef>

// ---------------- problem constants ----------------
#define DD0 41
#define DD1 20          // (41-3)/2+1
#define DD2 9           // (20-3)/2+1
#define HH  200
#define WW  176
#define HWs 35200
#define EPSV 1e-3f

#define N0MAX 30016
#define N1MAX 60032     // <= 2*N0
#define N2MAX 120064    // <= 2*M1
#define TCAP  65536     // per-tap pair capacity (>= max pairs per tap, proven)

#define MAP0_SZ (2*DD0*HWs)   // 2,886,400
#define MAP1_SZ (2*DD1*HWs)   // 1,408,000
#define MAP2_SZ (2*DD2*HWs)   //   633,600
#define OUT_TOTAL (2*64*DD2*HWs)

// ---------------- device scratch ----------------
__device__ __align__(16) int   g_map0[MAP0_SZ];
__device__ __align__(16) int   g_map1[MAP1_SZ];
__device__ __align__(16) int   g_map2[MAP2_SZ];

__device__ __align__(16) float g_Y0[(size_t)N0MAX*64];
__device__ __align__(16) float g_Z1[(size_t)N1MAX*64];
__device__ __align__(16) float g_YA[(size_t)N1MAX*64];
__device__ __align__(16) float g_YB[(size_t)N1MAX*64];
__device__ __align__(16) float g_Z2[(size_t)N2MAX*64];

__device__ __align__(16) int4  g_c1[N1MAX];
__device__ __align__(16) int4  g_c2[N2MAX];

__device__ __align__(16) int2  g_p0[27*TCAP];
__device__ __align__(16) int2  g_p1[27*TCAP];
__device__ __align__(16) int2  g_zp1[3*TCAP];
__device__ __align__(16) int2  g_zp2[3*TCAP];
__device__ int   g_pc0[27];
__device__ int   g_pc1[27];
__device__ int   g_zc1[3];
__device__ int   g_zc2[3];
__device__ int   g_cnt[4];          // [0]=N0  [1]=M1  [2]=M2
__device__ float g_stats[5*128];    // per BN layer: 64 sums + 64 sumsqs

// ---------------- init (maps + counters only) ----------------
__global__ void k_init(int n0) {
    size_t tid = (size_t)blockIdx.x*blockDim.x + threadIdx.x;
    size_t stride = (size_t)gridDim.x*blockDim.x;
    int4 z4 = make_int4(0,0,0,0);
    int4* m0 = (int4*)g_map0;
    for (size_t i = tid; i < MAP0_SZ/4; i += stride) m0[i] = z4;
    int4* m1 = (int4*)g_map1;
    for (size_t i = tid; i < MAP1_SZ/4; i += stride) m1[i] = z4;
    int4* m2 = (int4*)g_map2;
    for (size_t i = tid; i < MAP2_SZ/4; i += stride) m2[i] = z4;
    if (tid < 27) { g_pc0[tid] = 0; g_pc1[tid] = 0; }
    if (tid < 3)  { g_zc1[tid] = 0; g_zc2[tid] = 0; }
    if (tid < 5*128) g_stats[tid] = 0.0f;
    if (tid == 0) { g_cnt[0] = n0; g_cnt[1] = 0; g_cnt[2] = 0; g_cnt[3] = 0; }
}

// ---------------- map build (+ zero Y0 rows) ----------------
__global__ void k_map0(const int4* __restrict__ coors, int n0) {
    int i = blockIdx.x*256 + threadIdx.x;
    if (i >= n0) return;
    int4 c = coors[i];
    g_map0[((c.x*DD0 + c.y)*HH + c.z)*WW + c.w] = i + 1;
    float4 z = make_float4(0.f,0.f,0.f,0.f);
    float4* yp = (float4*)(g_Y0 + (size_t)i*64);
    #pragma unroll
    for (int q = 0; q < 16; q++) yp[q] = z;
}

__global__ void k_build0(const int4* __restrict__ coors, int n0) {
    int i = blockIdx.x*256 + threadIdx.x;
    if (i >= n0) return;
    int4 c = coors[i];
    int b = c.x, z = c.y, y = c.z, x = c.w;
    #pragma unroll
    for (int dz = -1; dz <= 1; dz++)
    #pragma unroll
    for (int dy = -1; dy <= 1; dy++)
    #pragma unroll
    for (int dx = -1; dx <= 1; dx++) {
        int t = (dz+1)*9 + (dy+1)*3 + (dx+1);
        if (t == 13) continue;
        int nz = z+dz, ny = y+dy, nx = x+dx;
        if (nz < 0 || nz >= DD0 || ny < 0 || ny >= HH || nx < 0 || nx >= WW) continue;
        int j = g_map0[((b*DD0 + nz)*HH + ny)*WW + nx] - 1;
        if (j >= 0) {
            int pos = atomicAdd(&g_pc0[t], 1);
            g_p0[t*TCAP + pos] = make_int2(j, i);
        }
    }
    #pragma unroll
    for (int kz = 0; kz < 3; kz++) {
        int tt = z - kz;
        if (tt >= 0 && (tt & 1) == 0) {
            int oz = tt >> 1;
            if (oz < DD1) g_map1[((b*DD1 + oz)*HH + y)*WW + x] = 1;
        }
    }
}

// z-conv pair build: input row -> output row per kz
__global__ void k_zbuild1(const int4* __restrict__ coors, int n0) {
    int i = blockIdx.x*256 + threadIdx.x;
    if (i >= n0) return;
    int4 c = coors[i];
    #pragma unroll
    for (int kz = 0; kz < 3; kz++) {
        int tt = c.y - kz;
        if (tt >= 0 && (tt & 1) == 0) {
            int oz = tt >> 1;
            if (oz < DD1) {
                int dst = g_map1[((c.x*DD1 + oz)*HH + c.z)*WW + c.w] - 2;
                if (dst >= 0) {
                    int pos = atomicAdd(&g_zc1[kz], 1);
                    g_zp1[kz*TCAP + pos] = make_int2(i, dst);
                }
            }
        }
    }
}

__global__ void k_zbuild2() {
    int r = blockIdx.x*256 + threadIdx.x;
    if (r >= g_cnt[1]) return;
    int4 c = g_c1[r];
    #pragma unroll
    for (int kz = 0; kz < 3; kz++) {
        int tt = c.y - kz;
        if (tt >= 0 && (tt & 1) == 0) {
            int oz = tt >> 1;
            if (oz < DD2) {
                int dst = g_map2[((c.x*DD2 + oz)*HH + c.z)*WW + c.w] - 2;
                if (dst >= 0) {
                    int pos = atomicAdd(&g_zc2[kz], 1);
                    g_zp2[kz*TCAP + pos] = make_int2(r, dst);
                }
            }
        }
    }
}

// subm stage-1 pair build + mark map2 + zero YA/YB rows
__global__ void k_build1() {
    int r = blockIdx.x*256 + threadIdx.x;
    if (r >= g_cnt[1]) return;
    int4 c = g_c1[r];
    int b = c.x, z = c.y, y = c.z, x = c.w;
    #pragma unroll
    for (int dz = -1; dz <= 1; dz++)
    #pragma unroll
    for (int dy = -1; dy <= 1; dy++)
    #pragma unroll
    for (int dx = -1; dx <= 1; dx++) {
        int t = (dz+1)*9 + (dy+1)*3 + (dx+1);
        if (t == 13) continue;
        int nz = z+dz, ny = y+dy, nx = x+dx;
        if (nz < 0 || nz >= DD1 || ny < 0 || ny >= HH || nx < 0 || nx >= WW) continue;
        int j = g_map1[((b*DD1 + nz)*HH + ny)*WW + nx] - 2;
        if (j >= 0) {
            int pos = atomicAdd(&g_pc1[t], 1);
            g_p1[t*TCAP + pos] = make_int2(j, r);
        }
    }
    #pragma unroll
    for (int kz = 0; kz < 3; kz++) {
        int tt = z - kz;
        if (tt >= 0 && (tt & 1) == 0) {
            int oz = tt >> 1;
            if (oz < DD2) g_map2[((b*DD2 + oz)*HH + y)*WW + x] = 1;
        }
    }
    float4 zf = make_float4(0.f,0.f,0.f,0.f);
    float4* ya = (float4*)(g_YA + (size_t)r*64);
    float4* yb = (float4*)(g_YB + (size_t)r*64);
    #pragma unroll
    for (int q = 0; q < 16; q++) { ya[q] = zf; yb[q] = zf; }
}

// ---------------- compact marked map -> row ids + coords (+ zero Z rows) ----------------
__global__ void k_compact(int which) {
    int* map   = which ? g_map2 : g_map1;
    int size4  = which ? MAP2_SZ/4 : MAP1_SZ/4;
    int D      = which ? DD2 : DD1;
    int4* cout = which ? g_c2 : g_c1;
    float* zbuf = which ? g_Z2 : g_Z1;
    int ci     = which ? 2 : 1;
    __shared__ int scnt, sbase;
    int gid = blockIdx.x*256 + threadIdx.x;
    if (threadIdx.x == 0) scnt = 0;
    __syncthreads();
    bool in = gid < size4;
    int4 v = make_int4(0,0,0,0);
    if (in) v = ((int4*)map)[gid];
    int vals[4] = {v.x, v.y, v.z, v.w};
    int my = (vals[0]==1) + (vals[1]==1) + (vals[2]==1) + (vals[3]==1);
    int loc = 0;
    if (my) loc = atomicAdd(&scnt, my);
    __syncthreads();
    if (threadIdx.x == 0) sbase = scnt ? atomicAdd(&g_cnt[ci], scnt) : 0;
    __syncthreads();
    if (!in) return;
    if (my) {
        int idx = sbase + loc;
        int lin = gid*4;
        int outv[4];
        float4 zf = make_float4(0.f,0.f,0.f,0.f);
        #pragma unroll
        for (int q = 0; q < 4; q++) {
            if (vals[q] == 1) {
                int L = lin + q;
                int b = L / (D*HWs);
                int r = L % (D*HWs);
                int z = r / HWs;
                int rr = r % HWs;
                int y = rr / WW;
                int x = rr % WW;
                cout[idx] = make_int4(b, z, y, x);
                float4* zp = (float4*)(zbuf + (size_t)idx*64);
                #pragma unroll
                for (int qq = 0; qq < 16; qq++) zp[qq] = zf;
                outv[q] = idx + 2;
                idx++;
            } else outv[q] = 0;
        }
        ((int4*)map)[gid] = make_int4(outv[0], outv[1], outv[2], outv[3]);
    }
}

// ---------------- merged tiled conv kernel ----------------
// grid.y = taps; blockIdx.y==centerTap uses identity rows; blockIdx.y==skipTap
// exits immediately (used when center runs in a separate overlapping launch).
// All writes atomicAdd into zero-initialized Y.
// Tile: 64 rows x 64 channels per block of 256 threads; grid-stride tiles.
// If layer >= 0: BN(layer, count g_cnt[bnci])+ReLU applied to X while staging.
#define RP2 68
template<int K>
__global__ __launch_bounds__(256) void k_conv(const float* __restrict__ X,
        const float* __restrict__ Wsrc, float* __restrict__ Y,
        const int2* __restrict__ pairsB, const int* __restrict__ pcnt, int ci,
        int centerTap, int skipTap, int layer, int bnci,
        const float* __restrict__ gm, const float* __restrict__ bt) {
    extern __shared__ float sm[];
    float* sW = sm;               // K*64 floats
    float* sF = sm + K*64;        // K*RP2 floats, layout [k][row]
    __shared__ float ssc[64], sbi[64];

    constexpr int NQ4 = K/16;

    if ((int)blockIdx.y == skipTap) return;
    const bool isC = ((int)blockIdx.y == centerTap);
    const int total = isC ? g_cnt[ci] : pcnt[blockIdx.y];
    if ((int)blockIdx.x * 64 >= total) return;   // idle block: no weight load
    const int2* pairs = pairsB + (size_t)blockIdx.y*TCAP;
    const float* Wp = Wsrc + (size_t)blockIdx.y*(K*64);

    if (layer >= 0 && threadIdx.x < 64) {
        int c = threadIdx.x;
        float cn = fmaxf((float)g_cnt[bnci], 1.0f);
        float mean = g_stats[layer*128 + c] / cn;
        float var  = g_stats[layer*128 + 64 + c] / cn - mean*mean;
        float sc   = gm[c] * rsqrtf(var + EPSV);
        ssc[c] = sc;
        sbi[c] = bt[c] - mean*sc;
    }
    for (int i = threadIdx.x; i < K*16; i += 256)
        ((float4*)sW)[i] = ((const float4*)Wp)[i];

    const float4* Xv = (const float4*)X;
    const int p  = threadIdx.x & 63;
    const int g  = threadIdx.x >> 6;
    const int cq = threadIdx.x & 15;
    const int rg = threadIdx.x >> 4;
    const int gstride = gridDim.x * 64;

    float4 st[NQ4];
    auto prefetch = [&](int pb) {
        if (pb >= total) return;
        int pnr = total - pb; if (pnr > 64) pnr = 64;
        if (p >= pnr) {
            #pragma unroll
            for (int qi = 0; qi < NQ4; qi++) st[qi] = make_float4(0.f,0.f,0.f,0.f);
            return;
        }
        int row = isC ? (pb + p) : pairs[pb + p].x;
        const float4* xp = Xv + (size_t)row*(K/4) + g*NQ4;
        #pragma unroll
        for (int qi = 0; qi < NQ4; qi++) st[qi] = xp[qi];
    };

    prefetch(blockIdx.x*64);

    for (int base = blockIdx.x*64; base < total; base += gstride) {
        int nr = min(64, total - base);
        __syncthreads();     // sW/BN coeffs ready (iter0) / prev compute done
        #pragma unroll
        for (int qi = 0; qi < NQ4; qi++) {
            int q4 = g*NQ4 + qi;
            float4 v = st[qi];
            if (layer >= 0) {
                int c4 = (q4*4) & 63;
                v.x = fmaxf(fmaf(v.x, ssc[c4+0], sbi[c4+0]), 0.f);
                v.y = fmaxf(fmaf(v.y, ssc[c4+1], sbi[c4+1]), 0.f);
                v.z = fmaxf(fmaf(v.z, ssc[c4+2], sbi[c4+2]), 0.f);
                v.w = fmaxf(fmaf(v.w, ssc[c4+3], sbi[c4+3]), 0.f);
            }
            float* d = sF + (q4*4)*RP2 + p;
            d[0] = v.x; d[RP2] = v.y;
            d[2*RP2] = v.z; d[3*RP2] = v.w;
        }
        __syncthreads();
        prefetch(base + gstride);

        float4 a0 = make_float4(0.f,0.f,0.f,0.f);
        float4 a1 = a0, a2 = a0, a3 = a0;
        const float4* wv = (const float4*)sW;
        float4 wA = wv[cq];
        float4 fA = *(const float4*)(sF + rg*4);
        #pragma unroll 8
        for (int k = 0; k < K; k++) {
            float4 wB, fB;
            if (k < K-1) {
                wB = wv[(k+1)*16 + cq];
                fB = *(const float4*)(sF + (k+1)*RP2 + rg*4);
            }
            a0.x += fA.x*wA.x; a0.y += fA.x*wA.y; a0.z += fA.x*wA.z; a0.w += fA.x*wA.w;
            a1.x += fA.y*wA.x; a1.y += fA.y*wA.y; a1.z += fA.y*wA.z; a1.w += fA.y*wA.w;
            a2.x += fA.z*wA.x; a2.y += fA.z*wA.y; a2.z += fA.z*wA.z; a2.w += fA.z*wA.w;
            a3.x += fA.w*wA.x; a3.y += fA.w*wA.y; a3.z += fA.w*wA.z; a3.w += fA.w*wA.w;
            wA = wB; fA = fB;
        }
        int p0 = rg*4;
        #pragma unroll
        for (int r = 0; r < 4; r++) {
            if (p0 + r < nr) {
                float4 a = (r==0)?a0:(r==1)?a1:(r==2)?a2:a3;
                int dst = isC ? (base + p0 + r) : pairs[base + p0 + r].y;
                float* yp = Y + (size_t)dst*64 + cq*4;
                atomicAdd(yp+0, a.x); atomicAdd(yp+1, a.y);
                atomicAdd(yp+2, a.z); atomicAdd(yp+3, a.w);
            }
        }
    }
}

// ---------------- BN stats ----------------
__global__ void k_stats(const float* __restrict__ X, int ci, int layer) {
    __shared__ float ss[512];
    int cnt = g_cnt[ci];
    int c = threadIdx.x & 63, g = threadIdx.x >> 6;
    float s = 0.f, q = 0.f;
    for (int r = blockIdx.x*4 + g; r < cnt; r += gridDim.x*4) {
        float v = X[(size_t)r*64 + c];
        s += v; q += v*v;
    }
    ss[threadIdx.x] = s; ss[256 + threadIdx.x] = q;
    __syncthreads();
    if (threadIdx.x < 64) {
        s = ss[threadIdx.x] + ss[threadIdx.x+64] + ss[threadIdx.x+128] + ss[threadIdx.x+192];
        q = ss[256+threadIdx.x] + ss[320+threadIdx.x] + ss[384+threadIdx.x] + ss[448+threadIdx.x];
        atomicAdd(&g_stats[layer*128 + threadIdx.x], s);
        atomicAdd(&g_stats[layer*128 + 64 + threadIdx.x], q);
    }
}

// ---------------- final: BN + ReLU + dense scatter (fused) ----------------
__global__ void k_out(const float* __restrict__ Z2, float* __restrict__ out,
                      const float* __restrict__ gm, const float* __restrict__ bt) {
    __shared__ float ssc[64], sbi[64];
    int cnt = g_cnt[2];
    float cn = fmaxf((float)cnt, 1.0f);
    if (threadIdx.x < 64) {
        int c = threadIdx.x;
        float mean = g_stats[512 + c] / cn;
        float var  = g_stats[512 + 64 + c] / cn - mean*mean;
        float sc   = gm[c] * rsqrtf(var + EPSV);
        ssc[c] = sc;
        sbi[c] = bt[c] - mean*sc;
    }
    __syncthreads();
    const int tot4 = OUT_TOTAL/4;
    for (int e4 = blockIdx.x*blockDim.x + threadIdx.x; e4 < tot4;
         e4 += gridDim.x*blockDim.x) {
        int e = e4 * 4;
        int x  = e % WW;
        int t1 = e / WW;
        int y  = t1 % HH;
        int t2 = t1 / HH;
        int cz = t2 % (64*DD2);
        int b  = t2 / (64*DD2);
        int c  = cz / DD2;
        int z  = cz - c*DD2;
        float sc = ssc[c], bi = sbi[c];
        int midx = ((b*DD2 + z)*HH + y)*WW + x;
        int4 m = *reinterpret_cast<const int4*>(g_map2 + midx);
        float4 o;
        int j;
        j = m.x - 2; o.x = (j >= 0) ? fmaxf(fmaf(Z2[(size_t)j*64 + c], sc, bi), 0.f) : 0.f;
        j = m.y - 2; o.y = (j >= 0) ? fmaxf(fmaf(Z2[(size_t)j*64 + c], sc, bi), 0.f) : 0.f;
        j = m.z - 2; o.z = (j >= 0) ? fmaxf(fmaf(Z2[(size_t)j*64 + c], sc, bi), 0.f) : 0.f;
        j = m.w - 2; o.w = (j >= 0) ? fmaxf(fmaf(Z2[(size_t)j*64 + c], sc, bi), 0.f) : 0.f;
        ((float4*)out)[e4] = o;
    }
}

// ---------------- launch ----------------
extern "C" void kernel_launch(void* const* d_in, const int* in_sizes, int n_in,
                              void* d_out, int out_size) {
    const float* vox   = (const float*)d_in[0];
    const int4*  coors = (const int4*) d_in[1];
    const float* w0    = (const float*)d_in[3];
    const float* gg0   = (const float*)d_in[4];
    const float* bb0   = (const float*)d_in[5];
    const float* ws1   = (const float*)d_in[6];
    const float* ggs1  = (const float*)d_in[7];
    const float* bbs1  = (const float*)d_in[8];
    const float* w1a   = (const float*)d_in[9];
    const float* gg1a  = (const float*)d_in[10];
    const float* bb1a  = (const float*)d_in[11];
    const float* w1b   = (const float*)d_in[12];
    const float* gg1b  = (const float*)d_in[13];
    const float* bb1b  = (const float*)d_in[14];
    const float* ws2   = (const float*)d_in[15];
    const float* ggs2  = (const float*)d_in[16];
    const float* bbs2  = (const float*)d_in[17];
    float* out = (float*)d_out;
    int n0 = in_sizes[0] / 128;

    void *pY0, *pZ1, *pYA, *pYB, *pZ2, *pp0, *pp1, *pzp1, *pzp2,
         *ppc0, *ppc1, *pzc1, *pzc2;
    cudaGetSymbolAddress(&pY0, g_Y0);
    cudaGetSymbolAddress(&pZ1, g_Z1);
    cudaGetSymbolAddress(&pYA, g_YA);
    cudaGetSymbolAddress(&pYB, g_YB);
    cudaGetSymbolAddress(&pZ2, g_Z2);
    cudaGetSymbolAddress(&pp0, g_p0);
    cudaGetSymbolAddress(&pp1, g_p1);
    cudaGetSymbolAddress(&pzp1, g_zp1);
    cudaGetSymbolAddress(&pzp2, g_zp2);
    cudaGetSymbolAddress(&ppc0, g_pc0);
    cudaGetSymbolAddress(&ppc1, g_pc1);
    cudaGetSymbolAddress(&pzc1, g_zc1);
    cudaGetSymbolAddress(&pzc2, g_zc2);
    float* Y0 = (float*)pY0; float* Z1 = (float*)pZ1;
    float* YA = (float*)pYA; float* YB = (float*)pYB; float* Z2 = (float*)pZ2;
    const int2* P0 = (const int2*)pp0;  const int2* P1 = (const int2*)pp1;
    const int2* ZP1 = (const int2*)pzp1; const int2* ZP2 = (const int2*)pzp2;
    const int* PC0 = (const int*)ppc0;  const int* PC1 = (const int*)ppc1;
    const int* ZC1 = (const int*)pzc1;  const int* ZC2 = (const int*)pzc2;

    // second stream + events (created once; no device memory allocation)
    static cudaStream_t sB = nullptr;
    static cudaEvent_t evFork = nullptr, evB0 = nullptr, evZ1 = nullptr,
                       evB1 = nullptr, evZ2 = nullptr;
    if (sB == nullptr) {
        cudaStreamCreateWithFlags(&sB, cudaStreamNonBlocking);
        cudaEventCreateWithFlags(&evFork, cudaEventDisableTiming);
        cudaEventCreateWithFlags(&evB0,   cudaEventDisableTiming);
        cudaEventCreateWithFlags(&evZ1,   cudaEventDisableTiming);
        cudaEventCreateWithFlags(&evB1,   cudaEventDisableTiming);
        cudaEventCreateWithFlags(&evZ2,   cudaEventDisableTiming);
    }
    cudaStream_t s0 = 0;   // legacy default stream (harness captures this)

    // dynamic smem = K*(64+RP2)*4 = K*528 bytes
    cudaFuncSetAttribute(k_conv<128>, cudaFuncAttributeMaxDynamicSharedMemorySize, 128*528);
    cudaFuncSetAttribute(k_conv<64>,  cudaFuncAttributeMaxDynamicSharedMemorySize, 64*528);

    int gb0 = (n0 + 255) / 256;
    int gtc = (n0 + 127) / 128;         // conv0 center: 2 tiles/block (235)
    int gts = (N1MAX + 127) / 128;      // stage-1 subm: 2 tiles/block (469)

    // ---- serial prologue on s0 (map0 only; build0 moves to track B) ----
    k_init<<<1024, 256, 0, s0>>>(n0);
    k_map0<<<gb0, 256, 0, s0>>>(coors, n0);

    // ---- fork after map0: track B builds all pair lists / maps ----
    cudaEventRecord(evFork, s0);
    cudaStreamWaitEvent(sB, evFork, 0);

    // track B: build0 -> [evB0] -> compact1 -> zbuild1 -> [evZ1] -> build1 ->
    //          [evB1] -> compact2 -> zbuild2 -> [evZ2]
    k_build0<<<gb0, 256, 0, sB>>>(coors, n0);
    cudaEventRecord(evB0, sB);
    k_compact<<<MAP1_SZ/4/256, 256, 0, sB>>>(0);
    k_zbuild1<<<gb0, 256, 0, sB>>>(coors, n0);
    cudaEventRecord(evZ1, sB);
    k_build1<<<(N1MAX+255)/256, 256, 0, sB>>>();
    cudaEventRecord(evB1, sB);
    k_compact<<<(MAP2_SZ/4 + 255)/256, 256, 0, sB>>>(1);
    k_zbuild2<<<(N1MAX+255)/256, 256, 0, sB>>>();
    cudaEventRecord(evZ2, sB);

    // track A (s0): conv0 CENTER immediately (needs only map0's Y0 zero + vox)
    // Wsrc points at tap-13 weights; blockIdx.y = 0 = centerTap.
    k_conv<128><<<dim3(gtc,1), 256, 128*528, s0>>>(vox, w0 + (size_t)13*128*64, Y0,
            P0, PC0, 0, 0, -1, -1, 0, nullptr, nullptr);

    // conv0 TAPS (needs build0's pair lists); center tap 13 skipped
    cudaStreamWaitEvent(s0, evB0, 0);
    k_conv<128><<<dim3(16,27), 256, 128*528, s0>>>(vox, w0, Y0,
            P0, PC0, 0, -1, 13, -1, 0, nullptr, nullptr);
    k_stats<<<256, 256, 0, s0>>>(Y0, 0, 0);

    // stride-z conv 1 (needs zbuild1/compact1 from track B)
    cudaStreamWaitEvent(s0, evZ1, 0);
    k_conv<64><<<dim3(96,3), 256, 64*528, s0>>>(Y0, ws1, Z1,
            ZP1, ZC1, 1, -1, -1, 0, 0, gg0, bb0);
    k_stats<<<256, 256, 0, s0>>>(Z1, 1, 1);

    // subm1a (needs build1 pairs + YA zeroed), merged 27 taps, 2 tiles/block
    cudaStreamWaitEvent(s0, evB1, 0);
    k_conv<64><<<dim3(gts,27), 256, 64*528, s0>>>(Z1, w1a, YA,
            P1, PC1, 1, 13, -1, 1, 1, ggs1, bbs1);
    k_stats<<<256, 256, 0, s0>>>(YA, 1, 2);

    // subm1b, merged 27 taps
    k_conv<64><<<dim3(gts,27), 256, 64*528, s0>>>(YA, w1b, YB,
            P1, PC1, 1, 13, -1, 2, 1, gg1a, bb1a);
    k_stats<<<256, 256, 0, s0>>>(YB, 1, 3);

    // stride-z conv 2 (needs compact2/zbuild2 from track B)
    cudaStreamWaitEvent(s0, evZ2, 0);
    k_conv<64><<<dim3(192,3), 256, 64*528, s0>>>(YB, ws2, Z2,
            ZP2, ZC2, 2, -1, -1, 3, 1, gg1b, bb1b);
    k_stats<<<256, 256, 0, s0>>>(Z2, 2, 4);

    // fused BN4 + ReLU + dense scatter
    k_out<<<2368, 256, 0, s0>>>(Z2, out, ggs2, bbs2);

    (void)n_in; (void)out_size;
}

// round 16
// speedup vs baseline: 1.1704x; 1.0766x over previous
#include <cuda_runtime.h>
#include <cstddef>

// ---------------- problem constants ----------------
#define DD0 41
#define DD1 20          // (41-3)/2+1
#define DD2 9           // (20-3)/2+1
#define HH  200
#define WW  176
#define HWs 35200
#define EPSV 1e-3f

#define N0MAX 30016
#define N1MAX 60032     // <= 2*N0
#define N2MAX 120064    // <= 2*M1
#define TCAP  65536     // per-tap pair capacity (>= max pairs per tap, proven)

#define MAP0_SZ (2*DD0*HWs)   // 2,886,400
#define MAP1_SZ (2*DD1*HWs)   // 1,408,000
#define MAP2_SZ (2*DD2*HWs)   //   633,600
#define OUT_TOTAL (2*64*DD2*HWs)

// ---------------- device scratch ----------------
__device__ __align__(16) int   g_map0[MAP0_SZ];
__device__ __align__(16) int   g_map1[MAP1_SZ];
__device__ __align__(16) int   g_map2[MAP2_SZ];

__device__ __align__(16) float g_Y0[(size_t)N0MAX*64];
__device__ __align__(16) float g_Z1[(size_t)N1MAX*64];
__device__ __align__(16) float g_YA[(size_t)N1MAX*64];
__device__ __align__(16) float g_YB[(size_t)N1MAX*64];
__device__ __align__(16) float g_Z2[(size_t)N2MAX*64];

__device__ __align__(16) int4  g_c1[N1MAX];
__device__ __align__(16) int4  g_c2[N2MAX];

__device__ __align__(16) int2  g_p0[27*TCAP];
__device__ __align__(16) int2  g_p1[27*TCAP];
__device__ __align__(16) int2  g_zp1[3*TCAP];
__device__ __align__(16) int2  g_zp2[3*TCAP];
__device__ int   g_pc0[27];
__device__ int   g_pc1[27];
__device__ int   g_zc1[3];
__device__ int   g_zc2[3];
__device__ int   g_cnt[4];          // [0]=N0  [1]=M1  [2]=M2
__device__ float g_stats[5*128];    // per BN layer: 64 sums + 64 sumsqs

// ---------------- init A: map0 + counters (serial, before map0) ----------------
__global__ void k_initA(int n0) {
    size_t tid = (size_t)blockIdx.x*blockDim.x + threadIdx.x;
    size_t stride = (size_t)gridDim.x*blockDim.x;
    int4 z4 = make_int4(0,0,0,0);
    int4* m0 = (int4*)g_map0;
    for (size_t i = tid; i < MAP0_SZ/4; i += stride) m0[i] = z4;
    if (tid < 27) { g_pc0[tid] = 0; g_pc1[tid] = 0; }
    if (tid < 3)  { g_zc1[tid] = 0; g_zc2[tid] = 0; }
    if (tid < 5*128) g_stats[tid] = 0.0f;
    if (tid == 0) { g_cnt[0] = n0; g_cnt[1] = 0; g_cnt[2] = 0; g_cnt[3] = 0; }
}

// ---------------- init B: map1 + map2 (stream B, before build0) ----------------
__global__ void k_initB() {
    size_t tid = (size_t)blockIdx.x*blockDim.x + threadIdx.x;
    size_t stride = (size_t)gridDim.x*blockDim.x;
    int4 z4 = make_int4(0,0,0,0);
    int4* m1 = (int4*)g_map1;
    for (size_t i = tid; i < MAP1_SZ/4; i += stride) m1[i] = z4;
    int4* m2 = (int4*)g_map2;
    for (size_t i = tid; i < MAP2_SZ/4; i += stride) m2[i] = z4;
}

// ---------------- map build (+ zero Y0 rows) ----------------
__global__ void k_map0(const int4* __restrict__ coors, int n0) {
    int i = blockIdx.x*256 + threadIdx.x;
    if (i >= n0) return;
    int4 c = coors[i];
    g_map0[((c.x*DD0 + c.y)*HH + c.z)*WW + c.w] = i + 1;
    float4 z = make_float4(0.f,0.f,0.f,0.f);
    float4* yp = (float4*)(g_Y0 + (size_t)i*64);
    #pragma unroll
    for (int q = 0; q < 16; q++) yp[q] = z;
}

__global__ void k_build0(const int4* __restrict__ coors, int n0) {
    int i = blockIdx.x*256 + threadIdx.x;
    if (i >= n0) return;
    int4 c = coors[i];
    int b = c.x, z = c.y, y = c.z, x = c.w;
    #pragma unroll
    for (int dz = -1; dz <= 1; dz++)
    #pragma unroll
    for (int dy = -1; dy <= 1; dy++)
    #pragma unroll
    for (int dx = -1; dx <= 1; dx++) {
        int t = (dz+1)*9 + (dy+1)*3 + (dx+1);
        if (t == 13) continue;
        int nz = z+dz, ny = y+dy, nx = x+dx;
        if (nz < 0 || nz >= DD0 || ny < 0 || ny >= HH || nx < 0 || nx >= WW) continue;
        int j = g_map0[((b*DD0 + nz)*HH + ny)*WW + nx] - 1;
        if (j >= 0) {
            int pos = atomicAdd(&g_pc0[t], 1);
            g_p0[t*TCAP + pos] = make_int2(j, i);
        }
    }
    #pragma unroll
    for (int kz = 0; kz < 3; kz++) {
        int tt = z - kz;
        if (tt >= 0 && (tt & 1) == 0) {
            int oz = tt >> 1;
            if (oz < DD1) g_map1[((b*DD1 + oz)*HH + y)*WW + x] = 1;
        }
    }
}

// z-conv pair build: input row -> output row per kz
__global__ void k_zbuild1(const int4* __restrict__ coors, int n0) {
    int i = blockIdx.x*256 + threadIdx.x;
    if (i >= n0) return;
    int4 c = coors[i];
    #pragma unroll
    for (int kz = 0; kz < 3; kz++) {
        int tt = c.y - kz;
        if (tt >= 0 && (tt & 1) == 0) {
            int oz = tt >> 1;
            if (oz < DD1) {
                int dst = g_map1[((c.x*DD1 + oz)*HH + c.z)*WW + c.w] - 2;
                if (dst >= 0) {
                    int pos = atomicAdd(&g_zc1[kz], 1);
                    g_zp1[kz*TCAP + pos] = make_int2(i, dst);
                }
            }
        }
    }
}

__global__ void k_zbuild2() {
    int r = blockIdx.x*256 + threadIdx.x;
    if (r >= g_cnt[1]) return;
    int4 c = g_c1[r];
    #pragma unroll
    for (int kz = 0; kz < 3; kz++) {
        int tt = c.y - kz;
        if (tt >= 0 && (tt & 1) == 0) {
            int oz = tt >> 1;
            if (oz < DD2) {
                int dst = g_map2[((c.x*DD2 + oz)*HH + c.z)*WW + c.w] - 2;
                if (dst >= 0) {
                    int pos = atomicAdd(&g_zc2[kz], 1);
                    g_zp2[kz*TCAP + pos] = make_int2(r, dst);
                }
            }
        }
    }
}

// subm stage-1 pair build + mark map2 + zero YA/YB rows
__global__ void k_build1() {
    int r = blockIdx.x*256 + threadIdx.x;
    if (r >= g_cnt[1]) return;
    int4 c = g_c1[r];
    int b = c.x, z = c.y, y = c.z, x = c.w;
    #pragma unroll
    for (int dz = -1; dz <= 1; dz++)
    #pragma unroll
    for (int dy = -1; dy <= 1; dy++)
    #pragma unroll
    for (int dx = -1; dx <= 1; dx++) {
        int t = (dz+1)*9 + (dy+1)*3 + (dx+1);
        if (t == 13) continue;
        int nz = z+dz, ny = y+dy, nx = x+dx;
        if (nz < 0 || nz >= DD1 || ny < 0 || ny >= HH || nx < 0 || nx >= WW) continue;
        int j = g_map1[((b*DD1 + nz)*HH + ny)*WW + nx] - 2;
        if (j >= 0) {
            int pos = atomicAdd(&g_pc1[t], 1);
            g_p1[t*TCAP + pos] = make_int2(j, r);
        }
    }
    #pragma unroll
    for (int kz = 0; kz < 3; kz++) {
        int tt = z - kz;
        if (tt >= 0 && (tt & 1) == 0) {
            int oz = tt >> 1;
            if (oz < DD2) g_map2[((b*DD2 + oz)*HH + y)*WW + x] = 1;
        }
    }
    float4 zf = make_float4(0.f,0.f,0.f,0.f);
    float4* ya = (float4*)(g_YA + (size_t)r*64);
    float4* yb = (float4*)(g_YB + (size_t)r*64);
    #pragma unroll
    for (int q = 0; q < 16; q++) { ya[q] = zf; yb[q] = zf; }
}

// ---------------- compact marked map -> row ids + coords (+ zero Z rows) ----------------
__global__ void k_compact(int which) {
    int* map   = which ? g_map2 : g_map1;
    int size4  = which ? MAP2_SZ/4 : MAP1_SZ/4;
    int D      = which ? DD2 : DD1;
    int4* cout = which ? g_c2 : g_c1;
    float* zbuf = which ? g_Z2 : g_Z1;
    int ci     = which ? 2 : 1;
    __shared__ int scnt, sbase;
    int gid = blockIdx.x*256 + threadIdx.x;
    if (threadIdx.x == 0) scnt = 0;
    __syncthreads();
    bool in = gid < size4;
    int4 v = make_int4(0,0,0,0);
    if (in) v = ((int4*)map)[gid];
    int vals[4] = {v.x, v.y, v.z, v.w};
    int my = (vals[0]==1) + (vals[1]==1) + (vals[2]==1) + (vals[3]==1);
    int loc = 0;
    if (my) loc = atomicAdd(&scnt, my);
    __syncthreads();
    if (threadIdx.x == 0) sbase = scnt ? atomicAdd(&g_cnt[ci], scnt) : 0;
    __syncthreads();
    if (!in) return;
    if (my) {
        int idx = sbase + loc;
        int lin = gid*4;
        int outv[4];
        float4 zf = make_float4(0.f,0.f,0.f,0.f);
        #pragma unroll
        for (int q = 0; q < 4; q++) {
            if (vals[q] == 1) {
                int L = lin + q;
                int b = L / (D*HWs);
                int r = L % (D*HWs);
                int z = r / HWs;
                int rr = r % HWs;
                int y = rr / WW;
                int x = rr % WW;
                cout[idx] = make_int4(b, z, y, x);
                float4* zp = (float4*)(zbuf + (size_t)idx*64);
                #pragma unroll
                for (int qq = 0; qq < 16; qq++) zp[qq] = zf;
                outv[q] = idx + 2;
                idx++;
            } else outv[q] = 0;
        }
        ((int4*)map)[gid] = make_int4(outv[0], outv[1], outv[2], outv[3]);
    }
}

// ---------------- merged tiled conv kernel ----------------
// grid.y = taps; blockIdx.y==centerTap uses identity rows; blockIdx.y==skipTap
// exits immediately. All writes atomicAdd into zero-initialized Y.
// Tile: 64 rows x 64 channels per block of 256 threads; grid-stride tiles.
// If layer >= 0: BN(layer, count g_cnt[bnci])+ReLU applied to X while staging.
#define RP2 68
template<int K>
__global__ __launch_bounds__(256) void k_conv(const float* __restrict__ X,
        const float* __restrict__ Wsrc, float* __restrict__ Y,
        const int2* __restrict__ pairsB, const int* __restrict__ pcnt, int ci,
        int centerTap, int skipTap, int layer, int bnci,
        const float* __restrict__ gm, const float* __restrict__ bt) {
    extern __shared__ float sm[];
    float* sW = sm;               // K*64 floats
    float* sF = sm + K*64;        // K*RP2 floats, layout [k][row]
    __shared__ float ssc[64], sbi[64];

    constexpr int NQ4 = K/16;

    if ((int)blockIdx.y == skipTap) return;
    const bool isC = ((int)blockIdx.y == centerTap);
    const int total = isC ? g_cnt[ci] : pcnt[blockIdx.y];
    if ((int)blockIdx.x * 64 >= total) return;   // idle block: no weight load
    const int2* pairs = pairsB + (size_t)blockIdx.y*TCAP;
    const float* Wp = Wsrc + (size_t)blockIdx.y*(K*64);

    if (layer >= 0 && threadIdx.x < 64) {
        int c = threadIdx.x;
        float cn = fmaxf((float)g_cnt[bnci], 1.0f);
        float mean = g_stats[layer*128 + c] / cn;
        float var  = g_stats[layer*128 + 64 + c] / cn - mean*mean;
        float sc   = gm[c] * rsqrtf(var + EPSV);
        ssc[c] = sc;
        sbi[c] = bt[c] - mean*sc;
    }
    for (int i = threadIdx.x; i < K*16; i += 256)
        ((float4*)sW)[i] = ((const float4*)Wp)[i];

    const float4* Xv = (const float4*)X;
    const int p  = threadIdx.x & 63;
    const int g  = threadIdx.x >> 6;
    const int cq = threadIdx.x & 15;
    const int rg = threadIdx.x >> 4;
    const int gstride = gridDim.x * 64;

    float4 st[NQ4];
    auto prefetch = [&](int pb) {
        if (pb >= total) return;
        int pnr = total - pb; if (pnr > 64) pnr = 64;
        if (p >= pnr) {
            #pragma unroll
            for (int qi = 0; qi < NQ4; qi++) st[qi] = make_float4(0.f,0.f,0.f,0.f);
            return;
        }
        int row = isC ? (pb + p) : pairs[pb + p].x;
        const float4* xp = Xv + (size_t)row*(K/4) + g*NQ4;
        #pragma unroll
        for (int qi = 0; qi < NQ4; qi++) st[qi] = xp[qi];
    };

    prefetch(blockIdx.x*64);

    for (int base = blockIdx.x*64; base < total; base += gstride) {
        int nr = min(64, total - base);
        __syncthreads();     // sW/BN coeffs ready (iter0) / prev compute done
        #pragma unroll
        for (int qi = 0; qi < NQ4; qi++) {
            int q4 = g*NQ4 + qi;
            float4 v = st[qi];
            if (layer >= 0) {
                int c4 = (q4*4) & 63;
                v.x = fmaxf(fmaf(v.x, ssc[c4+0], sbi[c4+0]), 0.f);
                v.y = fmaxf(fmaf(v.y, ssc[c4+1], sbi[c4+1]), 0.f);
                v.z = fmaxf(fmaf(v.z, ssc[c4+2], sbi[c4+2]), 0.f);
                v.w = fmaxf(fmaf(v.w, ssc[c4+3], sbi[c4+3]), 0.f);
            }
            float* d = sF + (q4*4)*RP2 + p;
            d[0] = v.x; d[RP2] = v.y;
            d[2*RP2] = v.z; d[3*RP2] = v.w;
        }
        __syncthreads();
        prefetch(base + gstride);

        float4 a0 = make_float4(0.f,0.f,0.f,0.f);
        float4 a1 = a0, a2 = a0, a3 = a0;
        const float4* wv = (const float4*)sW;
        float4 wA = wv[cq];
        float4 fA = *(const float4*)(sF + rg*4);
        #pragma unroll 8
        for (int k = 0; k < K; k++) {
            float4 wB, fB;
            if (k < K-1) {
                wB = wv[(k+1)*16 + cq];
                fB = *(const float4*)(sF + (k+1)*RP2 + rg*4);
            }
            a0.x += fA.x*wA.x; a0.y += fA.x*wA.y; a0.z += fA.x*wA.z; a0.w += fA.x*wA.w;
            a1.x += fA.y*wA.x; a1.y += fA.y*wA.y; a1.z += fA.y*wA.z; a1.w += fA.y*wA.w;
            a2.x += fA.z*wA.x; a2.y += fA.z*wA.y; a2.z += fA.z*wA.z; a2.w += fA.z*wA.w;
            a3.x += fA.w*wA.x; a3.y += fA.w*wA.y; a3.z += fA.w*wA.z; a3.w += fA.w*wA.w;
            wA = wB; fA = fB;
        }
        int p0 = rg*4;
        #pragma unroll
        for (int r = 0; r < 4; r++) {
            if (p0 + r < nr) {
                float4 a = (r==0)?a0:(r==1)?a1:(r==2)?a2:a3;
                int dst = isC ? (base + p0 + r) : pairs[base + p0 + r].y;
                float* yp = Y + (size_t)dst*64 + cq*4;
                atomicAdd(yp+0, a.x); atomicAdd(yp+1, a.y);
                atomicAdd(yp+2, a.z); atomicAdd(yp+3, a.w);
            }
        }
    }
}

// ---------------- BN stats ----------------
__global__ void k_stats(const float* __restrict__ X, int ci, int layer) {
    __shared__ float ss[512];
    int cnt = g_cnt[ci];
    int c = threadIdx.x & 63, g = threadIdx.x >> 6;
    float s = 0.f, q = 0.f;
    for (int r = blockIdx.x*4 + g; r < cnt; r += gridDim.x*4) {
        float v = X[(size_t)r*64 + c];
        s += v; q += v*v;
    }
    ss[threadIdx.x] = s; ss[256 + threadIdx.x] = q;
    __syncthreads();
    if (threadIdx.x < 64) {
        s = ss[threadIdx.x] + ss[threadIdx.x+64] + ss[threadIdx.x+128] + ss[threadIdx.x+192];
        q = ss[256+threadIdx.x] + ss[320+threadIdx.x] + ss[384+threadIdx.x] + ss[448+threadIdx.x];
        atomicAdd(&g_stats[layer*128 + threadIdx.x], s);
        atomicAdd(&g_stats[layer*128 + 64 + threadIdx.x], q);
    }
}

// ---------------- final: BN + ReLU + dense scatter (fused, streaming stores) ----------------
__global__ void k_out(const float* __restrict__ Z2, float* __restrict__ out,
                      const float* __restrict__ gm, const float* __restrict__ bt) {
    __shared__ float ssc[64], sbi[64];
    int cnt = g_cnt[2];
    float cn = fmaxf((float)cnt, 1.0f);
    if (threadIdx.x < 64) {
        int c = threadIdx.x;
        float mean = g_stats[512 + c] / cn;
        float var  = g_stats[512 + 64 + c] / cn - mean*mean;
        float sc   = gm[c] * rsqrtf(var + EPSV);
        ssc[c] = sc;
        sbi[c] = bt[c] - mean*sc;
    }
    __syncthreads();
    const int tot4 = OUT_TOTAL/4;
    for (int e4 = blockIdx.x*blockDim.x + threadIdx.x; e4 < tot4;
         e4 += gridDim.x*blockDim.x) {
        int e = e4 * 4;
        int x  = e % WW;
        int t1 = e / WW;
        int y  = t1 % HH;
        int t2 = t1 / HH;
        int cz = t2 % (64*DD2);
        int b  = t2 / (64*DD2);
        int c  = cz / DD2;
        int z  = cz - c*DD2;
        float sc = ssc[c], bi = sbi[c];
        int midx = ((b*DD2 + z)*HH + y)*WW + x;
        int4 m = *reinterpret_cast<const int4*>(g_map2 + midx);
        float4 o;
        int j;
        j = m.x - 2; o.x = (j >= 0) ? fmaxf(fmaf(Z2[(size_t)j*64 + c], sc, bi), 0.f) : 0.f;
        j = m.y - 2; o.y = (j >= 0) ? fmaxf(fmaf(Z2[(size_t)j*64 + c], sc, bi), 0.f) : 0.f;
        j = m.z - 2; o.z = (j >= 0) ? fmaxf(fmaf(Z2[(size_t)j*64 + c], sc, bi), 0.f) : 0.f;
        j = m.w - 2; o.w = (j >= 0) ? fmaxf(fmaf(Z2[(size_t)j*64 + c], sc, bi), 0.f) : 0.f;
        __stcs(((float4*)out) + e4, o);   // evict-first: write-once output
    }
}

// ---------------- launch ----------------
extern "C" void kernel_launch(void* const* d_in, const int* in_sizes, int n_in,
                              void* d_out, int out_size) {
    const float* vox   = (const float*)d_in[0];
    const int4*  coors = (const int4*) d_in[1];
    const float* w0    = (const float*)d_in[3];
    const float* gg0   = (const float*)d_in[4];
    const float* bb0   = (const float*)d_in[5];
    const float* ws1   = (const float*)d_in[6];
    const float* ggs1  = (const float*)d_in[7];
    const float* bbs1  = (const float*)d_in[8];
    const float* w1a   = (const float*)d_in[9];
    const float* gg1a  = (const float*)d_in[10];
    const float* bb1a  = (const float*)d_in[11];
    const float* w1b   = (const float*)d_in[12];
    const float* gg1b  = (const float*)d_in[13];
    const float* bb1b  = (const float*)d_in[14];
    const float* ws2   = (const float*)d_in[15];
    const float* ggs2  = (const float*)d_in[16];
    const float* bbs2  = (const float*)d_in[17];
    float* out = (float*)d_out;
    int n0 = in_sizes[0] / 128;

    void *pY0, *pZ1, *pYA, *pYB, *pZ2, *pp0, *pp1, *pzp1, *pzp2,
         *ppc0, *ppc1, *pzc1, *pzc2;
    cudaGetSymbolAddress(&pY0, g_Y0);
    cudaGetSymbolAddress(&pZ1, g_Z1);
    cudaGetSymbolAddress(&pYA, g_YA);
    cudaGetSymbolAddress(&pYB, g_YB);
    cudaGetSymbolAddress(&pZ2, g_Z2);
    cudaGetSymbolAddress(&pp0, g_p0);
    cudaGetSymbolAddress(&pp1, g_p1);
    cudaGetSymbolAddress(&pzp1, g_zp1);
    cudaGetSymbolAddress(&pzp2, g_zp2);
    cudaGetSymbolAddress(&ppc0, g_pc0);
    cudaGetSymbolAddress(&ppc1, g_pc1);
    cudaGetSymbolAddress(&pzc1, g_zc1);
    cudaGetSymbolAddress(&pzc2, g_zc2);
    float* Y0 = (float*)pY0; float* Z1 = (float*)pZ1;
    float* YA = (float*)pYA; float* YB = (float*)pYB; float* Z2 = (float*)pZ2;
    const int2* P0 = (const int2*)pp0;  const int2* P1 = (const int2*)pp1;
    const int2* ZP1 = (const int2*)pzp1; const int2* ZP2 = (const int2*)pzp2;
    const int* PC0 = (const int*)ppc0;  const int* PC1 = (const int*)ppc1;
    const int* ZC1 = (const int*)pzc1;  const int* ZC2 = (const int*)pzc2;

    // second stream + events (created once; no device memory allocation)
    static cudaStream_t sB = nullptr;
    static cudaEvent_t evFork = nullptr, evMap0 = nullptr, evB0 = nullptr,
                       evZ1 = nullptr, evB1 = nullptr, evZ2 = nullptr;
    if (sB == nullptr) {
        cudaStreamCreateWithFlags(&sB, cudaStreamNonBlocking);
        cudaEventCreateWithFlags(&evFork, cudaEventDisableTiming);
        cudaEventCreateWithFlags(&evMap0, cudaEventDisableTiming);
        cudaEventCreateWithFlags(&evB0,   cudaEventDisableTiming);
        cudaEventCreateWithFlags(&evZ1,   cudaEventDisableTiming);
        cudaEventCreateWithFlags(&evB1,   cudaEventDisableTiming);
        cudaEventCreateWithFlags(&evZ2,   cudaEventDisableTiming);
    }
    cudaStream_t s0 = 0;   // legacy default stream (harness captures this)

    // dynamic smem = K*(64+RP2)*4 = K*528 bytes
    cudaFuncSetAttribute(k_conv<128>, cudaFuncAttributeMaxDynamicSharedMemorySize, 128*528);
    cudaFuncSetAttribute(k_conv<64>,  cudaFuncAttributeMaxDynamicSharedMemorySize, 64*528);

    int gb0 = (n0 + 255) / 256;
    int gtc = (n0 + 127) / 128;         // conv0 center: 2 tiles/block (235)
    int gts = (N1MAX + 127) / 128;      // stage-1 subm: 2 tiles/block (469)

    // ---- serial prologue on s0: only map0's dependencies ----
    k_initA<<<512, 256, 0, s0>>>(n0);
    cudaEventRecord(evFork, s0);
    cudaStreamWaitEvent(sB, evFork, 0);
    k_initB<<<512, 256, 0, sB>>>();       // map1/map2 zero, overlaps map0/conv0

    k_map0<<<gb0, 256, 0, s0>>>(coors, n0);
    cudaEventRecord(evMap0, s0);
    cudaStreamWaitEvent(sB, evMap0, 0);

    // track B: build0 -> [evB0] -> compact1 -> zbuild1 -> [evZ1] -> build1 ->
    //          [evB1] -> compact2 -> zbuild2 -> [evZ2]
    k_build0<<<gb0, 256, 0, sB>>>(coors, n0);
    cudaEventRecord(evB0, sB);
    k_compact<<<MAP1_SZ/4/256, 256, 0, sB>>>(0);
    k_zbuild1<<<gb0, 256, 0, sB>>>(coors, n0);
    cudaEventRecord(evZ1, sB);
    k_build1<<<(N1MAX+255)/256, 256, 0, sB>>>();
    cudaEventRecord(evB1, sB);
    k_compact<<<(MAP2_SZ/4 + 255)/256, 256, 0, sB>>>(1);
    k_zbuild2<<<(N1MAX+255)/256, 256, 0, sB>>>();
    cudaEventRecord(evZ2, sB);

    // track A (s0): conv0 CENTER immediately (needs only map0's Y0 zero + vox)
    k_conv<128><<<dim3(gtc,1), 256, 128*528, s0>>>(vox, w0 + (size_t)13*128*64, Y0,
            P0, PC0, 0, 0, -1, -1, 0, nullptr, nullptr);

    // conv0 TAPS (needs build0's pair lists); center tap 13 skipped
    cudaStreamWaitEvent(s0, evB0, 0);
    k_conv<128><<<dim3(16,27), 256, 128*528, s0>>>(vox, w0, Y0,
            P0, PC0, 0, -1, 13, -1, 0, nullptr, nullptr);
    k_stats<<<256, 256, 0, s0>>>(Y0, 0, 0);

    // stride-z conv 1 (needs zbuild1/compact1 from track B)
    cudaStreamWaitEvent(s0, evZ1, 0);
    k_conv<64><<<dim3(96,3), 256, 64*528, s0>>>(Y0, ws1, Z1,
            ZP1, ZC1, 1, -1, -1, 0, 0, gg0, bb0);
    k_stats<<<592, 256, 0, s0>>>(Z1, 1, 1);

    // subm1a (needs build1 pairs + YA zeroed), merged 27 taps, 2 tiles/block
    cudaStreamWaitEvent(s0, evB1, 0);
    k_conv<64><<<dim3(gts,27), 256, 64*528, s0>>>(Z1, w1a, YA,
            P1, PC1, 1, 13, -1, 1, 1, ggs1, bbs1);
    k_stats<<<592, 256, 0, s0>>>(YA, 1, 2);

    // subm1b, merged 27 taps
    k_conv<64><<<dim3(gts,27), 256, 64*528, s0>>>(YA, w1b, YB,
            P1, PC1, 1, 13, -1, 2, 1, gg1a, bb1a);
    k_stats<<<592, 256, 0, s0>>>(YB, 1, 3);

    // stride-z conv 2 (needs compact2/zbuild2 from track B)
    cudaStreamWaitEvent(s0, evZ2, 0);
    k_conv<64><<<dim3(192,3), 256, 64*528, s0>>>(YB, ws2, Z2,
            ZP2, ZC2, 2, -1, -1, 3, 1, gg1b, bb1b);
    k_stats<<<592, 256, 0, s0>>>(Z2, 2, 4);

    // fused BN4 + ReLU + dense scatter (streaming stores)
    k_out<<<2368, 256, 0, s0>>>(Z2, out, ggs2, bbs2);

    (void)n_in; (void)out_size;
}